// round 12
// baseline (speedup 1.0000x reference)
#include <cuda_runtime.h>

// QuantumRegression: 12-wire state-vector sim, two samples per block packed
// into f32x2 lanes. State = 4096 x ulonglong2 (X=f32x2, Y=f32x2) = 64KB in
// shared, storage index sw(e) = e ^ ((e>>4)&7) (conflict-free for all pass
// layouts at 16B granularity, affine-in-k addressing per pass).  [R7 maps]
//
// Structure (identical to the verified R11 kernel):
//  - Layer 0 folded into closed-form product-state init (prefix parity).
//  - Layers 1..3: 3 passes of 4 rotated wires; CNOT(3,4) folded into pass-B
//    store base, CNOT(7,8) deferred into next pass-A load base (conjugated).
//  - TANGENT-FORM rotations (4 f32x2 FMA per pair); dropped cosines folded
//    into the deferred-RZ diagonal tables (L1,L2) / alpha3^2 scalar (L3).
//  - Batch-shared constants hoisted into a one-block pre-kernel.
//  - <Z> @ head_w measurement fused into the final pass.
//
// THIS ROUND (single variable): __launch_bounds__(256, 3) -> <=84 regs,
// 3 CTAs/SM (smem 3*68.5KB = 205KB < 227KB), 24 warps/SM. The extra CTA
// de-phases the barrier-aligned LDS/STS bursts that leave the crossbar
// (the binding pipe, L1=71.4%) idle 29% of the time.

typedef unsigned long long u64;

#define NW 12

// ---- batch-shared constant staging (written by qsetup_kernel) ----
__device__ ulonglong2 g_gx[36];      // tangent gates (tn, -tn) layers 1..3
__device__ ulonglong2 g_dtab[96];    // diag*prod(c) tables, layers 1..2
__device__ float      g_wk[16];      // measurement weights wires 8..11
__device__ float      g_a3;          // layer-3 prod(c)^2
__device__ float4     g_l0[12];      // per-wire layer-0: c0, s0, cos(th), sin(th)

// ---- packed f32x2 helpers ----
static __device__ __forceinline__ u64 pack2(float lo, float hi) {
    u64 r; asm("mov.b64 %0, {%1, %2};" : "=l"(r) : "f"(lo), "f"(hi)); return r;
}
static __device__ __forceinline__ float2 unpack2(u64 v) {
    float2 r; asm("mov.b64 {%0, %1}, %2;" : "=f"(r.x), "=f"(r.y) : "l"(v)); return r;
}
static __device__ __forceinline__ u64 dup2(float v) { return pack2(v, v); }
static __device__ __forceinline__ u64 fma2(u64 a, u64 b, u64 c) {
    u64 d; asm("fma.rn.f32x2 %0, %1, %2, %3;" : "=l"(d) : "l"(a), "l"(b), "l"(c)); return d;
}
static __device__ __forceinline__ u64 mul2(u64 a, u64 b) {
    u64 d; asm("mul.rn.f32x2 %0, %1, %2;" : "=l"(d) : "l"(a), "l"(b)); return d;
}
static __device__ __forceinline__ u64 neg2(u64 a) { return a ^ 0x8000000080000000ULL; }

// staircase CNOT permutation on 4 bits (GF2-linear)
__device__ __host__ __forceinline__ constexpr int tau4(int k) {
    int b3 = (k >> 3) & 1;
    int b2 = ((k >> 2) & 1) ^ b3;
    int b1 = ((k >> 1) & 1) ^ b2;
    int b0 = (k & 1) ^ b1;
    return (b3 << 3) | (b2 << 2) | (b1 << 1) | b0;
}

// ---- shared memory layout (bytes) ----
#define SM_ST   0        // ulonglong2 st[4096]            : 65536
#define SM_G    65536    // ulonglong2 gx[3*12] (tn,-tn)   : 576
#define SM_D    66112    // ulonglong2 dtab[2*3*16]        : 1536
#define SM_V    67648    // ulonglong2 v[12][2]            : 384
#define SM_F    68032    // ulonglong2 F[16]               : 256
#define SM_HW   68288    // float hw[12]                   : 48
#define SM_WK   68336    // float wk[16]                   : 64
#define SM_RED  68400    // float2 red[8]                  : 64
#define SM_A3   68464    // float alpha3sq                 : 4
#define SMEM_BYTES 68480

// ---- tangent-form RX gate bundle: one LDS.128 ----
struct GX { u64 tn, ntn; };
static __device__ __forceinline__ GX load_gx(const ulonglong2* __restrict__ g) {
    GX r; ulonglong2 p = g[0]; r.tn = p.x; r.ntn = p.y; return r;
}

// tangent-form RX rotation on pair (i0, i1): 4 FMAs (scale c deferred)
static __device__ __forceinline__ void rxp(const GX& G, u64* X, u64* Y, int i0, int i1) {
    u64 X0 = X[i0], Y0 = Y[i0], X1 = X[i1], Y1 = Y[i1];
    X[i0] = fma2(G.tn, Y1, X0);
    Y[i0] = fma2(G.ntn, X1, Y0);
    X[i1] = fma2(G.tn, Y0, X1);
    Y[i1] = fma2(G.ntn, X0, Y1);
}

// apply window diagonal D[k] (includes window prod(c); batch-shared)
static __device__ __forceinline__ void diagp(const ulonglong2* __restrict__ dt,
                                             u64* X, u64* Y, int k) {
    ulonglong2 d = dt[k];
    u64 nx = fma2(d.x, X[k], neg2(mul2(d.y, Y[k])));
    u64 ny = fma2(d.x, Y[k], mul2(d.y, X[k]));
    X[k] = nx; Y[k] = ny;
}

// Per-pass element address masks (applied to swizzled storage index).
template<int P>
__device__ __forceinline__ int addr_of(int base, int k) {
    if (P == 0)      return base + (k << 8);                  // immediate offsets
    else if (P == 1) return base ^ ((k << 4) | (k & 7));      // compile-time XOR mask
    else             return base ^ k;                         // compile-time XOR mask
}

// One pass: 4 tangent-RX rotations, then per MODE:
//  MODE 0: window diagonal dt + CNOT-permuted store   (layers 1,2)
//  MODE 1: CNOT-permuted store, no diagonal           (layer 3, passes A,B)
//  MODE 2: fused measurement, no diagonal             (layer 3, pass C)
template<int P, int MODE>
__device__ __forceinline__ void do_pass(ulonglong2* __restrict__ st,
                                        const ulonglong2* __restrict__ g,
                                        const ulonglong2* __restrict__ dt,
                                        int loadBase, int storeBase,
                                        float whigh, const float* __restrict__ wk,
                                        int wkxor, float* pacc)
{
    u64 X[16], Y[16];
    GX G0 = load_gx(g);
#pragma unroll
    for (int j = 0; j < 8; j++) {              // load pair + first rotation
        ulonglong2 a = st[addr_of<P>(loadBase, j)];
        ulonglong2 b = st[addr_of<P>(loadBase, j | 8)];
        X[j] = a.x; Y[j] = a.y; X[j | 8] = b.x; Y[j | 8] = b.y;
        rxp(G0, X, Y, j, j | 8);
    }
    GX G1 = load_gx(g + 1);
#pragma unroll
    for (int j = 0; j < 16; j++) if (!(j & 4)) rxp(G1, X, Y, j, j | 4);
    GX G2 = load_gx(g + 2);
#pragma unroll
    for (int j = 0; j < 16; j++) if (!(j & 2)) rxp(G2, X, Y, j, j | 2);
    GX G3 = load_gx(g + 3);
#pragma unroll
    for (int j = 0; j < 16; j += 2) {          // last rotation + epilogue
        rxp(G3, X, Y, j, j | 1);
        if constexpr (MODE == 2) {             // fused measurement
            int i0 = tau4(j) ^ wkxor;
            float wl = whigh + wk[i0];
            u64 U = fma2(X[j], X[j], mul2(Y[j], Y[j]));
            float2 u = unpack2(U);
            pacc[0] = fmaf(u.x, wl, pacc[0]);
            pacc[1] = fmaf(u.y, wl, pacc[1]);
            int i1 = tau4(j | 1) ^ wkxor;
            wl = whigh + wk[i1];
            U = fma2(X[j | 1], X[j | 1], mul2(Y[j | 1], Y[j | 1]));
            u = unpack2(U);
            pacc[0] = fmaf(u.x, wl, pacc[0]);
            pacc[1] = fmaf(u.y, wl, pacc[1]);
        } else {
            if constexpr (MODE == 0) { diagp(dt, X, Y, j); diagp(dt, X, Y, j | 1); }
            ulonglong2 v0; v0.x = X[j];     v0.y = Y[j];
            st[addr_of<P>(storeBase, tau4(j))] = v0;
            ulonglong2 v1; v1.x = X[j | 1]; v1.y = Y[j | 1];
            st[addr_of<P>(storeBase, tau4(j | 1))] = v1;
        }
    }
}

// ---- pre-kernel: batch-shared constants, one block ----
__global__ void qsetup_kernel(const float* __restrict__ params,
                              const float* __restrict__ head_w)
{
    int t = threadIdx.x;
    if (t < 36) {                      // tangent coeffs: layer 1+t/12, wire t%12
        float th = params[12 + t];
        float c, s; sincosf(0.5f * th, &s, &c);
        float tn = s / c;
        ulonglong2 e; e.x = dup2(tn); e.y = dup2(-tn);
        g_gx[t] = e;
    }
    if (t == 40) {                     // layer-3 scalar: prod(c)^2
        float prod = 1.f;
#pragma unroll
        for (int w = 0; w < NW; w++) prod *= cosf(0.5f * params[36 + w]);
        g_a3 = prod * prod;
    }
    if (t >= 64 && t < 160) {          // diag tables: prod(c) * e^{i sum th_w bit_w}
        int i = t - 64;                // layer = i/48 (0->L1), window = (i%48)/16, m = i&15
        int l = i / 48, p = (i % 48) / 16, m = i & 15;
        const float* th = params + (l + 1) * NW + 4 * p;
        float phi = 0.f, cprod = 1.f;
#pragma unroll
        for (int q = 0; q < 4; q++) {
            if ((m >> (3 - q)) & 1) phi += th[q];
            cprod *= cosf(0.5f * th[q]);
        }
        float cp, sp; sincosf(phi, &sp, &cp);
        ulonglong2 e; e.x = dup2(cprod * cp); e.y = dup2(cprod * sp);
        g_dtab[i] = e;
    }
    if (t >= 160 && t < 176) {         // measurement weights for wires 8..11
        int m = t - 160;
        float w8 = head_w[8], w9 = head_w[9], w10 = head_w[10], w11 = head_w[11];
        g_wk[m] = ((m & 8) ? -w8 : w8) + ((m & 4) ? -w9 : w9)
                + ((m & 2) ? -w10 : w10) + ((m & 1) ? -w11 : w11);
    }
    if (t >= 176 && t < 188) {         // layer-0 per-wire param trig
        int w = t - 176;
        float c0, s0; sincosf(0.5f * params[w], &s0, &c0);
        g_l0[w] = make_float4(c0, s0, c0 * c0 - s0 * s0, 2.f * s0 * c0);
    }
}

__global__ void __launch_bounds__(256, 3)
qsim8_kernel(const float* __restrict__ inputs,
             const float* __restrict__ head_w,
             const float* __restrict__ head_b,
             float* __restrict__ out)
{
    extern __shared__ char sm[];
    ulonglong2* st   = (ulonglong2*)(sm + SM_ST);
    ulonglong2* gx   = (ulonglong2*)(sm + SM_G);
    ulonglong2* dtab = (ulonglong2*)(sm + SM_D);
    ulonglong2* vtab = (ulonglong2*)(sm + SM_V);
    ulonglong2* Ftab = (ulonglong2*)(sm + SM_F);
    float* hw  = (float*)(sm + SM_HW);
    float* wk  = (float*)(sm + SM_WK);
    float2* red = (float2*)(sm + SM_RED);
    float* a3  = (float*)(sm + SM_A3);

    const int b = blockIdx.x;
    const int t = threadIdx.x;

    // ---- phase 1: stage batch-shared constants (LDG->STS) + per-sample trig ----
    if (t < 36) gx[t] = g_gx[t];
    if (t >= 64 && t < 160) dtab[t - 64] = g_dtab[t - 64];
    if (t >= 160 && t < 176) wk[t - 160] = g_wk[t - 160];
    if (t == 176) a3[0] = g_a3;
    if (t < NW) {                      // layer-0 per-wire 2-vectors (both samples)
        int w = t;
        float4 l0 = g_l0[w];
        float c0 = l0.x, s0 = l0.y, cn = l0.z, sn = l0.w;
        float v0x[2], v0y[2], v1x[2], v1y[2];
#pragma unroll
        for (int j = 0; j < 2; j++) {
            float cy, sy; sincosf(0.5f * inputs[(2 * b + j) * NW + w], &sy, &cy);
            v0x[j] = c0 * cy;  v0y[j] = -s0 * sy;
            float zx = c0 * sy, zy = -s0 * cy;           // z = -i s cy + c sy
            v1x[j] = cn * zx - sn * zy;                   // e^{i th} * z
            v1y[j] = sn * zx + cn * zy;
        }
        ulonglong2 e0; e0.x = pack2(v0x[0], v0x[1]); e0.y = pack2(v0y[0], v0y[1]);
        ulonglong2 e1; e1.x = pack2(v1x[0], v1x[1]); e1.y = pack2(v1y[0], v1y[1]);
        vtab[(w << 1) | 0] = e0;
        vtab[(w << 1) | 1] = e1;
        hw[w] = head_w[w];
    }
    __syncthreads();

    // ---- phase 2: F table (wires 0..3 staircase products, per sample-pair) ----
    if (t < 16) {
        int c0 = (t >> 3) & 1, c1 = (t >> 2) & 1, c2 = (t >> 1) & 1, c3 = t & 1;
        int b0 = c0, b1 = c1 ^ c0, b2 = c2 ^ c1, b3 = c3 ^ c2;
        ulonglong2 a = vtab[0 | b0];
        u64 PX = a.x, PY = a.y;
        int bb[3] = {b1, b2, b3};
#pragma unroll
        for (int w = 1; w <= 3; w++) {
            ulonglong2 q = vtab[(w << 1) | bb[w - 1]];
            u64 nx = fma2(PX, q.x, neg2(mul2(PY, q.y)));
            u64 ny = fma2(PX, q.y, mul2(PY, q.x));
            PX = nx; PY = ny;
        }
        ulonglong2 f; f.x = PX; f.y = PY; Ftab[t] = f;
    }

    // per-thread bases (R7 maps, verified; cheap rematerializations from t)
    const int baseA  = t ^ ((t >> 4) & 7);              // pass-A canonical base
    const int tA2    = t ^ (((t >> 4) & 1) * 0xF);      // conjugated C78 deferral
    const int baseA2 = tA2 ^ ((tA2 >> 4) & 7);          // pass-A load base (L2,L3)
    const int baseB  = ((t >> 4) << 8) | (t & 15);
    const int baseBs = baseB ^ (((t >> 4) & 1) ? 0xF7 : 0);  // CNOT(3,4) fold
    const int baseC  = (t << 4) | (t & 7);
    const int wkxor  = (t & 1) ? 0xF : 0;               // CNOT(7,8) fold at measure

    // measurement weight for wires 0..7 (t bits 7..0, wire i <-> t bit 7-i)
    float whigh = 0.f;
#pragma unroll
    for (int m = 0; m < 8; m++) {
        float w = hw[7 - m];
        whigh += ((t >> m) & 1) ? -w : w;
    }
    __syncthreads();

    float pacc[2] = {0.f, 0.f};
    const ulonglong2* g1 = gx;            // layer 1 (12 gates)
    const ulonglong2* g2 = gx + 12;       // layer 2
    const ulonglong2* g3 = gx + 24;       // layer 3
    const ulonglong2* d1 = dtab;          // layer-1 diagonals (3 windows x 16)
    const ulonglong2* d2 = dtab + 48;     // layer-2 diagonals

    // ======== Layer 1, pass A: closed-form init + tan-rx chain + diag ====
    {
        u64 X[16], Y[16];
        int u = t ^ (t >> 1);             // u bit (11-w) = b_w for wires 5..11
        ulonglong2 p5 = vtab[(5 << 1) | ((u >> 6) & 1)];
        u64 PX = p5.x, PY = p5.y;
#pragma unroll
        for (int w = 6; w <= 11; w++) {
            ulonglong2 q = vtab[(w << 1) | ((u >> (11 - w)) & 1)];
            u64 nx = fma2(PX, q.x, neg2(mul2(PY, q.y)));
            u64 ny = fma2(PX, q.y, mul2(PY, q.x));
            PX = nx; PY = ny;
        }
        int t7 = (t >> 7) & 1;
        ulonglong2 q0 = vtab[(4 << 1) | t7];
        ulonglong2 q1 = vtab[(4 << 1) | (t7 ^ 1)];
        u64 R0X = fma2(PX, q0.x, neg2(mul2(PY, q0.y)));
        u64 R0Y = fma2(PX, q0.y, mul2(PY, q0.x));
        u64 R1X = fma2(PX, q1.x, neg2(mul2(PY, q1.y)));
        u64 R1Y = fma2(PX, q1.y, mul2(PY, q1.x));
        GX G0 = load_gx(g1);
#pragma unroll
        for (int j = 0; j < 8; j++) {     // build pair (j, j|8) then rotate it
            ulonglong2 Fk0 = Ftab[j];
            u64 QX = (j & 1) ? R1X : R0X;
            u64 QY = (j & 1) ? R1Y : R0Y;
            X[j] = fma2(Fk0.x, QX, neg2(mul2(Fk0.y, QY)));
            Y[j] = fma2(Fk0.x, QY, mul2(Fk0.y, QX));
            ulonglong2 Fk1 = Ftab[j | 8];
            X[j | 8] = fma2(Fk1.x, QX, neg2(mul2(Fk1.y, QY)));
            Y[j | 8] = fma2(Fk1.x, QY, mul2(Fk1.y, QX));
            rxp(G0, X, Y, j, j | 8);
        }
        GX G1 = load_gx(g1 + 1);
#pragma unroll
        for (int j = 0; j < 16; j++) if (!(j & 4)) rxp(G1, X, Y, j, j | 4);
        GX G2 = load_gx(g1 + 2);
#pragma unroll
        for (int j = 0; j < 16; j++) if (!(j & 2)) rxp(G2, X, Y, j, j | 2);
        GX G3 = load_gx(g1 + 3);
#pragma unroll
        for (int j = 0; j < 16; j += 2) { // last rotation + diagonal + store
            rxp(G3, X, Y, j, j | 1);
            diagp(d1, X, Y, j); diagp(d1, X, Y, j | 1);
            ulonglong2 v0; v0.x = X[j];     v0.y = Y[j];
            st[baseA + (tau4(j) << 8)] = v0;
            ulonglong2 v1; v1.x = X[j | 1]; v1.y = Y[j | 1];
            st[baseA + (tau4(j | 1) << 8)] = v1;
        }
    }
    __syncthreads();

    do_pass<1, 0>(st, g1 + 4, d1 + 16, baseB, baseBs, whigh, wk, 0, pacc); __syncthreads();
    do_pass<2, 0>(st, g1 + 8, d1 + 32, baseC, baseC,  whigh, wk, 0, pacc); __syncthreads();

    // ======== Layer 2 ========
    do_pass<0, 0>(st, g2,     d2,      baseA2, baseA,  whigh, wk, 0, pacc); __syncthreads();
    do_pass<1, 0>(st, g2 + 4, d2 + 16, baseB,  baseBs, whigh, wk, 0, pacc); __syncthreads();
    do_pass<2, 0>(st, g2 + 8, d2 + 32, baseC,  baseC,  whigh, wk, 0, pacc); __syncthreads();

    // ======== Layer 3 (tangent RX, scale deferred to alpha3^2) ========
    do_pass<0, 1>(st, g3,     nullptr, baseA2, baseA,  whigh, wk, 0, pacc); __syncthreads();
    do_pass<1, 1>(st, g3 + 4, nullptr, baseB,  baseBs, whigh, wk, 0, pacc); __syncthreads();
    do_pass<2, 2>(st, g3 + 8, nullptr, baseC,  baseC,  whigh, wk, wkxor, pacc);

    // ---- reduce both samples; apply deferred layer-3 scale ----
    float p0 = pacc[0], p1 = pacc[1];
#pragma unroll
    for (int o = 16; o; o >>= 1) {
        p0 += __shfl_xor_sync(0xFFFFFFFFu, p0, o);
        p1 += __shfl_xor_sync(0xFFFFFFFFu, p1, o);
    }
    if ((t & 31) == 0) red[t >> 5] = make_float2(p0, p1);
    __syncthreads();
    if (t < 2) {
        float s = 0.f;
#pragma unroll
        for (int w = 0; w < 8; w++) s += (t == 0) ? red[w].x : red[w].y;
        out[2 * b + t] = s * a3[0] + head_b[0];
    }
}

extern "C" void kernel_launch(void* const* d_in, const int* in_sizes, int n_in,
                              void* d_out, int out_size)
{
    const float* inputs = (const float*)d_in[0];
    const float* params = (const float*)d_in[1];
    const float* head_w = (const float*)d_in[2];
    const float* head_b = (const float*)d_in[3];
    float* out = (float*)d_out;

    cudaFuncSetAttribute(qsim8_kernel, cudaFuncAttributeMaxDynamicSharedMemorySize, SMEM_BYTES);
    qsetup_kernel<<<1, 192>>>(params, head_w);           // batch-shared constants
    int B2 = out_size / 2;                               // two samples per block
    qsim8_kernel<<<B2, 256, SMEM_BYTES>>>(inputs, head_w, head_b, out);
}

// round 13
// speedup vs baseline: 1.3807x; 1.3807x over previous
#include <cuda_runtime.h>

// QuantumRegression: 12-wire state-vector sim, two samples per block packed
// into f32x2 lanes. State = 4096 x ulonglong2 (X=f32x2, Y=f32x2) = 64KB in
// shared, storage index sw(a) = a ^ ((a>>4)&7).  [R7/R11 maps]
//
// SIX-PASS schedule via CNOT-chain conjugation:
//  - Layer 0 folded into closed-form product-state init (prefix parity).
//  - stair2 and stair3 deferred ENTIRELY into measurement weights: composed
//    perm = S^2 (S = prefix parity), parity sets P_w = {w, w-2, w-4, ...}.
//  - Layer-3 RX conjugated through stair2: rot3~(w) = exp(-i th/2 X_w X_{w+1})
//    (2-bit pair mask, same 4-FMA tangent cost, all mutually commuting).
//  - P1: init + rot1(w0-3)+diag1+stair1(tau)+C34 fold        [res bits 11-8]
//  - P2: rot1(w4-7)+diag1+stair1(tau)+C34 store fold          [res bits 7-4]
//  - P3: rot1(w8-11)+diag1+stair1(tau)+C78(in-reg)+rot2(w8-11)
//        +diag2+rot3~(w8-11); C78 residual folded into P4 load [res bits 3-0]
//  - P4: rot2(w4-7)+diag2+rot3~(w4-6)                         [res bits 7-4]
//  - P5: rot2(w0-3)+diag2+rot3~(w0-2)                         [res bits 11-8]
//  - P6: rot3~(w3),rot3~(w7) + fused S^2-weighted measurement [res bits 8,7,4,3]
//  5 loads + 5 stores of the state vs 8+8 previously (-37.5% smem traffic).
//  Tangent-form rotations; dropped cosines -> diag tables / alpha3^2 scalar.

typedef unsigned long long u64;

#define NW 12

// ---- batch-shared constant staging (written by qsetup_kernel) ----
__device__ ulonglong2 g_gx[36];      // tangent gates (tn, -tn) layers 1..3
__device__ ulonglong2 g_dtab[96];    // diag*prod(c) tables, layers 1..2
__device__ float      g_a3;          // layer-3 prod(c)^2
__device__ float4     g_l0[12];      // per-wire layer-0: c0, s0, cos(th), sin(th)

// ---- packed f32x2 helpers ----
static __device__ __forceinline__ u64 pack2(float lo, float hi) {
    u64 r; asm("mov.b64 %0, {%1, %2};" : "=l"(r) : "f"(lo), "f"(hi)); return r;
}
static __device__ __forceinline__ float2 unpack2(u64 v) {
    float2 r; asm("mov.b64 {%0, %1}, %2;" : "=f"(r.x), "=f"(r.y) : "l"(v)); return r;
}
static __device__ __forceinline__ u64 dup2(float v) { return pack2(v, v); }
static __device__ __forceinline__ u64 fma2(u64 a, u64 b, u64 c) {
    u64 d; asm("fma.rn.f32x2 %0, %1, %2, %3;" : "=l"(d) : "l"(a), "l"(b), "l"(c)); return d;
}
static __device__ __forceinline__ u64 mul2(u64 a, u64 b) {
    u64 d; asm("mul.rn.f32x2 %0, %1, %2;" : "=l"(d) : "l"(a), "l"(b)); return d;
}
static __device__ __forceinline__ u64 neg2(u64 a) { return a ^ 0x8000000080000000ULL; }

// staircase CNOT permutation on 4 bits (GF2-linear)
__device__ __host__ __forceinline__ constexpr int tau4(int k) {
    int b3 = (k >> 3) & 1;
    int b2 = ((k >> 2) & 1) ^ b3;
    int b1 = ((k >> 1) & 1) ^ b2;
    int b0 = (k & 1) ^ b1;
    return (b3 << 3) | (b2 << 2) | (b1 << 1) | b0;
}

// ---- shared memory layout (bytes) ----
#define SM_ST   0        // ulonglong2 st[4096]            : 65536
#define SM_G    65536    // ulonglong2 gx[3*12] (tn,-tn)   : 576
#define SM_D    66112    // ulonglong2 dtab[2*3*16]        : 1536
#define SM_V    67648    // ulonglong2 v[12][2]            : 384
#define SM_F    68032    // ulonglong2 F[16]               : 256
#define SM_HW   68288    // float hw[12]                   : 48
#define SM_RED  68352    // float2 red[8]                  : 64
#define SM_A3   68416    // float alpha3sq                 : 4
#define SMEM_BYTES 68432

// ---- tangent-form gate bundle ----
struct GX { u64 tn, ntn; };
static __device__ __forceinline__ GX load_gx(const ulonglong2* __restrict__ g) {
    GX r; ulonglong2 p = g[0]; r.tn = p.x; r.ntn = p.y; return r;
}

// tangent-form rotation on pair (i0, i1): 4 FMAs (scale c deferred)
static __device__ __forceinline__ void rxp(const GX& G, u64* X, u64* Y, int i0, int i1) {
    u64 X0 = X[i0], Y0 = Y[i0], X1 = X[i1], Y1 = Y[i1];
    X[i0] = fma2(G.tn, Y1, X0);
    Y[i0] = fma2(G.ntn, X1, Y0);
    X[i1] = fma2(G.tn, Y0, X1);
    Y[i1] = fma2(G.ntn, X0, Y1);
}

// rotation over all 16 regs with pair mask M (each pair once via MSB test)
template<int M, int MSB>
static __device__ __forceinline__ void rotm(const GX& G, u64* X, u64* Y) {
#pragma unroll
    for (int k = 0; k < 16; k++) if (!(k & MSB)) rxp(G, X, Y, k, k ^ M);
}

// apply diagonal entry d to slot k
static __device__ __forceinline__ void diag1e(ulonglong2 d, u64* X, u64* Y, int k) {
    u64 nx = fma2(d.x, X[k], neg2(mul2(d.y, Y[k])));
    u64 ny = fma2(d.x, Y[k], mul2(d.y, X[k]));
    X[k] = nx; Y[k] = ny;
}

// k-nibble address image for pass-B map (k at bits 7-4; swizzle folds k&7)
__device__ __host__ __forceinline__ constexpr int offk1(int k) {
    return (k << 4) | (k & 7);
}
// k image for pass-6 map (k bits at amp bits 8,7,4,3; swizzle folds bit4->bit0)
__device__ __host__ __forceinline__ constexpr int offk6(int k) {
    return (((k >> 3) & 1) << 8) | (((k >> 2) & 1) << 7) | (((k >> 1) & 1) << 4)
         | ((k & 1) << 3) | ((k >> 1) & 1);
}

// ---- pre-kernel: batch-shared constants, one block ----
__global__ void qsetup_kernel(const float* __restrict__ params,
                              const float* __restrict__ head_w)
{
    int t = threadIdx.x;
    if (t < 36) {                      // tangent coeffs: layer 1+t/12, wire t%12
        float th = params[12 + t];
        float c, s; sincosf(0.5f * th, &s, &c);
        float tn = s / c;
        ulonglong2 e; e.x = dup2(tn); e.y = dup2(-tn);
        g_gx[t] = e;
    }
    if (t == 40) {                     // layer-3 scalar: prod(c)^2
        float prod = 1.f;
#pragma unroll
        for (int w = 0; w < NW; w++) prod *= cosf(0.5f * params[36 + w]);
        g_a3 = prod * prod;
    }
    if (t >= 64 && t < 160) {          // diag tables: prod(c) * e^{i sum th_w bit_w}
        int i = t - 64;                // layer = i/48 (0->L1), window = (i%48)/16, m = i&15
        int l = i / 48, p = (i % 48) / 16, m = i & 15;
        const float* th = params + (l + 1) * NW + 4 * p;
        float phi = 0.f, cprod = 1.f;
#pragma unroll
        for (int q = 0; q < 4; q++) {
            if ((m >> (3 - q)) & 1) phi += th[q];
            cprod *= cosf(0.5f * th[q]);
        }
        float cp, sp; sincosf(phi, &sp, &cp);
        ulonglong2 e; e.x = dup2(cprod * cp); e.y = dup2(cprod * sp);
        g_dtab[i] = e;
    }
    if (t >= 176 && t < 188) {         // layer-0 per-wire param trig
        int w = t - 176;
        float c0, s0; sincosf(0.5f * params[w], &s0, &c0);
        g_l0[w] = make_float4(c0, s0, c0 * c0 - s0 * s0, 2.f * s0 * c0);
    }
}

__global__ void __launch_bounds__(256, 2)
qsim9_kernel(const float* __restrict__ inputs,
             const float* __restrict__ head_w,
             const float* __restrict__ head_b,
             float* __restrict__ out)
{
    extern __shared__ char sm[];
    ulonglong2* st   = (ulonglong2*)(sm + SM_ST);
    ulonglong2* gx   = (ulonglong2*)(sm + SM_G);
    ulonglong2* dtab = (ulonglong2*)(sm + SM_D);
    ulonglong2* vtab = (ulonglong2*)(sm + SM_V);
    ulonglong2* Ftab = (ulonglong2*)(sm + SM_F);
    float* hw  = (float*)(sm + SM_HW);
    float2* red = (float2*)(sm + SM_RED);
    float* a3  = (float*)(sm + SM_A3);

    const int b = blockIdx.x;
    const int t = threadIdx.x;

    // ---- stage batch-shared constants + per-sample trig ----
    if (t < 36) gx[t] = g_gx[t];
    if (t >= 64 && t < 160) dtab[t - 64] = g_dtab[t - 64];
    if (t == 176) a3[0] = g_a3;
    if (t < NW) {                      // layer-0 per-wire 2-vectors (both samples)
        int w = t;
        float4 l0 = g_l0[w];
        float c0 = l0.x, s0 = l0.y, cn = l0.z, sn = l0.w;
        float v0x[2], v0y[2], v1x[2], v1y[2];
#pragma unroll
        for (int j = 0; j < 2; j++) {
            float cy, sy; sincosf(0.5f * inputs[(2 * b + j) * NW + w], &sy, &cy);
            v0x[j] = c0 * cy;  v0y[j] = -s0 * sy;
            float zx = c0 * sy, zy = -s0 * cy;           // z = -i s cy + c sy
            v1x[j] = cn * zx - sn * zy;                   // e^{i th} * z
            v1y[j] = sn * zx + cn * zy;
        }
        ulonglong2 e0; e0.x = pack2(v0x[0], v0x[1]); e0.y = pack2(v0y[0], v0y[1]);
        ulonglong2 e1; e1.x = pack2(v1x[0], v1x[1]); e1.y = pack2(v1y[0], v1y[1]);
        vtab[(w << 1) | 0] = e0;
        vtab[(w << 1) | 1] = e1;
        hw[w] = head_w[w];
    }
    __syncthreads();

    // ---- F table (wires 0..3 staircase products, per sample-pair) ----
    if (t < 16) {
        int c0 = (t >> 3) & 1, c1 = (t >> 2) & 1, c2 = (t >> 1) & 1, c3 = t & 1;
        int b0 = c0, b1 = c1 ^ c0, b2 = c2 ^ c1, b3 = c3 ^ c2;
        ulonglong2 a = vtab[0 | b0];
        u64 PX = a.x, PY = a.y;
        int bb[3] = {b1, b2, b3};
#pragma unroll
        for (int w = 1; w <= 3; w++) {
            ulonglong2 q = vtab[(w << 1) | bb[w - 1]];
            u64 nx = fma2(PX, q.x, neg2(mul2(PY, q.y)));
            u64 ny = fma2(PX, q.y, mul2(PY, q.x));
            PX = nx; PY = ny;
        }
        ulonglong2 f; f.x = PX; f.y = PY; Ftab[t] = f;
    }

    // ---- per-thread bases (R7/R11 maps; verified conflict-free) ----
    const int baseA  = t ^ ((t >> 4) & 7);              // res 11-8: a = k<<8 | t
    const int baseB  = ((t >> 4) << 8) | (t & 15);      // res 7-4
    const int baseBs = baseB ^ (((t >> 4) & 1) ? 0xF7 : 0);  // C34_l1 fold (P2 store)
    const int baseC  = (t << 4) | (t & 7);              // res 3-0: a = t<<4 | k
    // P6 map: a = [t7 t6 t5 | k3 k2 | t4 t3 | k1 | k0 | t2 t1 t0], swizzled
    const int base6  = (((t & 0xE0) << 4) | ((t & 0x18) << 2) | (t & 7)) ^ ((t >> 2) & 6);
    const int cxC    = (t & 1) ? 0xF : 0;               // C78_l1 in-reg (P3): wire7 = t0

    // ---- S^2 measurement weight partials (stair2*stair3 folded) ----
    // parity set P_w = {w, w-2, ...}; thread wires {0,1,2,5,6,9,10,11}
    float S0, SA, SB, SC, SD;
    {
        float T80 = (__popc(t & 0x80) & 1) ? -1.f : 1.f;
        float T40 = (__popc(t & 0x40) & 1) ? -1.f : 1.f;
        float TA0 = (__popc(t & 0xA0) & 1) ? -1.f : 1.f;
        float T50 = (__popc(t & 0x50) & 1) ? -1.f : 1.f;
        float TA8 = (__popc(t & 0xA8) & 1) ? -1.f : 1.f;
        float T54 = (__popc(t & 0x54) & 1) ? -1.f : 1.f;
        float TAA = (__popc(t & 0xAA) & 1) ? -1.f : 1.f;
        float T55 = (__popc(t & 0x55) & 1) ? -1.f : 1.f;
        S0 = hw[0] * T80 + hw[1] * T40 + hw[2] * TA0;     // local part: none
        SA = hw[3] * T40 + hw[5] * T50;                   // local: k3 (wire 3)
        SB = hw[4] * TA0 + hw[6] * TA8;                   // local: k2 (wire 4)
        SC = hw[7] * T50 + hw[9] * T54 + hw[11] * T55;    // local: k1^k3 (wires 7,3)
        SD = hw[8] * TA8 + hw[10] * TAA;                  // local: k0^k2 (wires 8,4)
    }
    __syncthreads();

    const ulonglong2* g1 = gx;            // layer-1 tangents (wires 0..11)
    const ulonglong2* g2 = gx + 12;       // layer 2
    const ulonglong2* g3 = gx + 24;       // layer 3 (conjugated rot3~)
    const ulonglong2* d1 = dtab;          // layer-1 diagonals (3 windows x 16)
    const ulonglong2* d2 = dtab + 48;     // layer-2 diagonals

    // ======== P1: init + rot1(w0-3) + diag1 + stair1 store  [res 11-8] ====
    {
        u64 X[16], Y[16];
        int u = t ^ (t >> 1);             // u bit (11-w) = b_w for wires 5..11
        ulonglong2 p5 = vtab[(5 << 1) | ((u >> 6) & 1)];
        u64 PX = p5.x, PY = p5.y;
#pragma unroll
        for (int w = 6; w <= 11; w++) {
            ulonglong2 q = vtab[(w << 1) | ((u >> (11 - w)) & 1)];
            u64 nx = fma2(PX, q.x, neg2(mul2(PY, q.y)));
            u64 ny = fma2(PX, q.y, mul2(PY, q.x));
            PX = nx; PY = ny;
        }
        int t7 = (t >> 7) & 1;
        ulonglong2 q0 = vtab[(4 << 1) | t7];
        ulonglong2 q1 = vtab[(4 << 1) | (t7 ^ 1)];
        u64 R0X = fma2(PX, q0.x, neg2(mul2(PY, q0.y)));
        u64 R0Y = fma2(PX, q0.y, mul2(PY, q0.x));
        u64 R1X = fma2(PX, q1.x, neg2(mul2(PY, q1.y)));
        u64 R1Y = fma2(PX, q1.y, mul2(PY, q1.x));
        GX G0 = load_gx(g1);
#pragma unroll
        for (int j = 0; j < 8; j++) {     // build pair (j, j|8), rotate wire0
            ulonglong2 Fk0 = Ftab[j];
            u64 QX = (j & 1) ? R1X : R0X;
            u64 QY = (j & 1) ? R1Y : R0Y;
            X[j] = fma2(Fk0.x, QX, neg2(mul2(Fk0.y, QY)));
            Y[j] = fma2(Fk0.x, QY, mul2(Fk0.y, QX));
            ulonglong2 Fk1 = Ftab[j | 8];
            X[j | 8] = fma2(Fk1.x, QX, neg2(mul2(Fk1.y, QY)));
            Y[j | 8] = fma2(Fk1.x, QY, mul2(Fk1.y, QX));
            rxp(G0, X, Y, j, j | 8);
        }
        GX G1 = load_gx(g1 + 1); rotm<4, 4>(G1, X, Y);
        GX G2 = load_gx(g1 + 2); rotm<2, 2>(G2, X, Y);
        GX G3 = load_gx(g1 + 3); rotm<1, 1>(G3, X, Y);
#pragma unroll
        for (int k = 0; k < 16; k++) {    // diag1(A) + stair1 store
            diag1e(d1[k], X, Y, k);
            ulonglong2 v; v.x = X[k]; v.y = Y[k];
            st[baseA + (tau4(k) << 8)] = v;
        }
    }
    __syncthreads();

    // ======== P2: rot1(w4-7) + diag1 + stair1 + C34 fold  [res 7-4] ====
    {
        u64 X[16], Y[16];
        GX G4 = load_gx(g1 + 4);
#pragma unroll
        for (int j = 0; j < 8; j++) {
            ulonglong2 a = st[baseB ^ offk1(j)];
            ulonglong2 c = st[baseB ^ offk1(j | 8)];
            X[j] = a.x; Y[j] = a.y; X[j | 8] = c.x; Y[j | 8] = c.y;
            rxp(G4, X, Y, j, j | 8);
        }
        GX G5 = load_gx(g1 + 5); rotm<4, 4>(G5, X, Y);
        GX G6 = load_gx(g1 + 6); rotm<2, 2>(G6, X, Y);
        GX G7 = load_gx(g1 + 7); rotm<1, 1>(G7, X, Y);
#pragma unroll
        for (int k = 0; k < 16; k++) {
            diag1e(d1[16 + k], X, Y, k);
            ulonglong2 v; v.x = X[k]; v.y = Y[k];
            st[baseBs ^ offk1(tau4(k))] = v;
        }
    }
    __syncthreads();

    // ======== P3: rot1(w8-11)+diag1+stair1+C78(in-reg)+rot2+diag2+rot3~ ====
    // registers stay in original-k labels; final label = tau4(k) ^ 0xF*t0.
    // rot2/rot3~ pair masks mapped through tau4^-1; store at image(tau4(k)),
    // leaving the 0xF*t0 residual to be corrected at P4's load.
    {
        u64 X[16], Y[16];
        GX G8 = load_gx(g1 + 8);
#pragma unroll
        for (int j = 0; j < 8; j++) {
            ulonglong2 a = st[baseC ^ j];
            ulonglong2 c = st[baseC ^ (j | 8)];
            X[j] = a.x; Y[j] = a.y; X[j | 8] = c.x; Y[j | 8] = c.y;
            rxp(G8, X, Y, j, j | 8);
        }
        GX G9  = load_gx(g1 + 9);  rotm<4, 4>(G9, X, Y);
        GX G10 = load_gx(g1 + 10); rotm<2, 2>(G10, X, Y);
        GX G11 = load_gx(g1 + 11); rotm<1, 1>(G11, X, Y);
#pragma unroll
        for (int k = 0; k < 16; k++) diag1e(d1[32 + k], X, Y, k);  // diag1(C), idx k
        // rot2(w8-11) in final-label space: original offsets tau4^-1(8,4,2,1)=12,6,3,1
        GX H8  = load_gx(g2 + 8);  rotm<12, 8>(H8, X, Y);
        GX H9  = load_gx(g2 + 9);  rotm<6, 4>(H9, X, Y);
        GX H10 = load_gx(g2 + 10); rotm<3, 2>(H10, X, Y);
        GX H11 = load_gx(g2 + 11); rotm<1, 1>(H11, X, Y);
        // diag2(C) at final labels tau4(k)^cxC
#pragma unroll
        for (int k = 0; k < 16; k++) diag1e(d2[32 + (tau4(k) ^ cxC)], X, Y, k);
        // rot3~(w8..11): final masks {3,2},{2,1},{1,0},{0} -> orig 0xA,5,2,1
        GX J8  = load_gx(g3 + 8);  rotm<10, 8>(J8, X, Y);
        GX J9  = load_gx(g3 + 9);  rotm<5, 4>(J9, X, Y);
        GX J10 = load_gx(g3 + 10); rotm<2, 2>(J10, X, Y);
        GX J11 = load_gx(g3 + 11); rotm<1, 1>(J11, X, Y);
#pragma unroll
        for (int k = 0; k < 16; k++) {
            ulonglong2 v; v.x = X[k]; v.y = Y[k];
            st[baseC ^ tau4(k)] = v;
        }
    }
    __syncthreads();

    // ======== P4: rot2(w4-7)+diag2+rot3~(w4-6)  [res 7-4] ====
    // load corrects P3's residual: true label = stored ^ 0xF*bit4; bit4 = k0.
    {
        u64 X[16], Y[16];
        GX H4 = load_gx(g2 + 4);
#pragma unroll
        for (int j = 0; j < 8; j++) {
            int fx = (j & 1) ? 0xF : 0;
            ulonglong2 a = st[baseB ^ offk1(j) ^ fx];
            ulonglong2 c = st[baseB ^ offk1(j | 8) ^ fx];
            X[j] = a.x; Y[j] = a.y; X[j | 8] = c.x; Y[j | 8] = c.y;
            rxp(H4, X, Y, j, j | 8);
        }
        GX H5 = load_gx(g2 + 5); rotm<4, 4>(H5, X, Y);
        GX H6 = load_gx(g2 + 6); rotm<2, 2>(H6, X, Y);
        GX H7 = load_gx(g2 + 7); rotm<1, 1>(H7, X, Y);
#pragma unroll
        for (int k = 0; k < 16; k++) diag1e(d2[16 + k], X, Y, k);
        GX J4 = load_gx(g3 + 4); rotm<12, 8>(J4, X, Y);   // w4: bits{7,6}
        GX J5 = load_gx(g3 + 5); rotm<6, 4>(J5, X, Y);    // w5: bits{6,5}
        GX J6 = load_gx(g3 + 6); rotm<3, 2>(J6, X, Y);    // w6: bits{5,4}
#pragma unroll
        for (int k = 0; k < 16; k++) {
            ulonglong2 v; v.x = X[k]; v.y = Y[k];
            st[baseB ^ offk1(k)] = v;                     // canonical store
        }
    }
    __syncthreads();

    // ======== P5: rot2(w0-3)+diag2+rot3~(w0-2)  [res 11-8] ====
    {
        u64 X[16], Y[16];
        GX H0 = load_gx(g2);
#pragma unroll
        for (int j = 0; j < 8; j++) {
            ulonglong2 a = st[baseA + (j << 8)];
            ulonglong2 c = st[baseA + ((j | 8) << 8)];
            X[j] = a.x; Y[j] = a.y; X[j | 8] = c.x; Y[j | 8] = c.y;
            rxp(H0, X, Y, j, j | 8);
        }
        GX H1 = load_gx(g2 + 1); rotm<4, 4>(H1, X, Y);
        GX H2 = load_gx(g2 + 2); rotm<2, 2>(H2, X, Y);
        GX H3 = load_gx(g2 + 3); rotm<1, 1>(H3, X, Y);
#pragma unroll
        for (int k = 0; k < 16; k++) diag1e(d2[k], X, Y, k);
        GX J0 = load_gx(g3);     rotm<12, 8>(J0, X, Y);   // w0: bits{11,10}
        GX J1 = load_gx(g3 + 1); rotm<6, 4>(J1, X, Y);    // w1: bits{10,9}
        GX J2 = load_gx(g3 + 2); rotm<3, 2>(J2, X, Y);    // w2: bits{9,8}
#pragma unroll
        for (int k = 0; k < 16; k++) {
            ulonglong2 v; v.x = X[k]; v.y = Y[k];
            st[baseA + (k << 8)] = v;
        }
    }
    __syncthreads();

    // ======== P6: rot3~(w3), rot3~(w7) + fused measurement  [res 8,7,4,3] ====
    float pacc[2] = {0.f, 0.f};
    {
        u64 X[16], Y[16];
#pragma unroll
        for (int k = 0; k < 16; k++) {
            ulonglong2 a = st[base6 ^ offk6(k)];
            X[k] = a.x; Y[k] = a.y;
        }
        GX J3 = load_gx(g3 + 3); rotm<12, 8>(J3, X, Y);   // w3: bits{8,7}=k3,k2
        GX J7 = load_gx(g3 + 7); rotm<3, 2>(J7, X, Y);    // w7: bits{4,3}=k1,k0
#pragma unroll
        for (int k = 0; k < 16; k++) {
            float wl = S0
                + (((k >> 3) & 1) ? -SA : SA)
                + (((k >> 2) & 1) ? -SB : SB)
                + ((((k >> 1) ^ (k >> 3)) & 1) ? -SC : SC)
                + (((k ^ (k >> 2)) & 1) ? -SD : SD);
            u64 U = fma2(X[k], X[k], mul2(Y[k], Y[k]));
            float2 u = unpack2(U);
            pacc[0] = fmaf(u.x, wl, pacc[0]);
            pacc[1] = fmaf(u.y, wl, pacc[1]);
        }
    }

    // ---- reduce both samples; apply deferred layer-3 scale ----
    float p0 = pacc[0], p1 = pacc[1];
#pragma unroll
    for (int o = 16; o; o >>= 1) {
        p0 += __shfl_xor_sync(0xFFFFFFFFu, p0, o);
        p1 += __shfl_xor_sync(0xFFFFFFFFu, p1, o);
    }
    if ((t & 31) == 0) red[t >> 5] = make_float2(p0, p1);
    __syncthreads();
    if (t < 2) {
        float s = 0.f;
#pragma unroll
        for (int w = 0; w < 8; w++) s += (t == 0) ? red[w].x : red[w].y;
        out[2 * b + t] = s * a3[0] + head_b[0];
    }
}

extern "C" void kernel_launch(void* const* d_in, const int* in_sizes, int n_in,
                              void* d_out, int out_size)
{
    const float* inputs = (const float*)d_in[0];
    const float* params = (const float*)d_in[1];
    const float* head_w = (const float*)d_in[2];
    const float* head_b = (const float*)d_in[3];
    float* out = (float*)d_out;

    cudaFuncSetAttribute(qsim9_kernel, cudaFuncAttributeMaxDynamicSharedMemorySize, SMEM_BYTES);
    qsetup_kernel<<<1, 192>>>(params, head_w);           // batch-shared constants
    int B2 = out_size / 2;                               // two samples per block
    qsim9_kernel<<<B2, 256, SMEM_BYTES>>>(inputs, head_w, head_b, out);
}

// round 14
// speedup vs baseline: 1.4082x; 1.0199x over previous
#include <cuda_runtime.h>
#include <cuda_fp16.h>

// QuantumRegression: 12-wire state-vector sim, two samples per block packed
// into f32x2 lanes. Registers/math are fp32 (f32x2); the SHARED state is
// stored fp16: one u64 per amp = (X half2, Y half2) = 8 bytes (was 16).
// Storage index sw8(a) = a ^ ((a>>4)&0xF) ^ ((a>>8)&0xF) -- both upper
// nibbles folded into the low nibble; verified conflict-free for every pass
// layout at LDS.64 16-lane phase granularity.
//
// SIX-PASS schedule via CNOT-chain conjugation (algebra identical to R13):
//  - Layer 0 folded into closed-form product-state init (prefix parity).
//  - stair2/stair3 deferred into measurement weights (S^2 parity sets).
//  - Layer-3 RX conjugated through stair2: rot3~(w) = exp(-i th/2 X_w X_{w+1}).
//  - P1: init + rot1(w0-3)+diag1+stair1 store            [res bits 11-8]
//  - P2: rot1(w4-7)+diag1+stair1+C34 store fold           [res bits 7-4]
//  - P3: rot1(w8-11)+diag1+stair1+C78(in-reg)+rot2(w8-11)
//        +diag2+rot3~(w8-11); residual folded into P4 load [res bits 3-0]
//  - P4: rot2(w4-7)+diag2+rot3~(w4-6)                     [res bits 7-4]
//  - P5: rot2(w0-3)+diag2+rot3~(w0-2)                     [res bits 11-8]
//  - P6: rot3~(w3),rot3~(w7) + fused S^2 measurement      [res bits 8,7,4,3]
//    P6 t-bit map re-chosen (t3 at amp bit 11) so sw8 keeps the low nibble
//    injective; S-masks re-derived for the new wire<->bit sources.
//  Tangent-form rotations; dropped cosines -> diag tables / alpha3^2 scalar.

typedef unsigned long long u64;

#define NW 12

// ---- batch-shared constant staging (written by qsetup_kernel) ----
__device__ ulonglong2 g_gx[36];      // tangent gates (tn, -tn) layers 1..3
__device__ ulonglong2 g_dtab[96];    // diag*prod(c) tables, layers 1..2
__device__ float      g_a3;          // layer-3 prod(c)^2
__device__ float4     g_l0[12];      // per-wire layer-0: c0, s0, cos(th), sin(th)

// ---- packed f32x2 helpers ----
static __device__ __forceinline__ u64 pack2(float lo, float hi) {
    u64 r; asm("mov.b64 %0, {%1, %2};" : "=l"(r) : "f"(lo), "f"(hi)); return r;
}
static __device__ __forceinline__ float2 unpack2(u64 v) {
    float2 r; asm("mov.b64 {%0, %1}, %2;" : "=f"(r.x), "=f"(r.y) : "l"(v)); return r;
}
static __device__ __forceinline__ u64 dup2(float v) { return pack2(v, v); }
static __device__ __forceinline__ u64 fma2(u64 a, u64 b, u64 c) {
    u64 d; asm("fma.rn.f32x2 %0, %1, %2, %3;" : "=l"(d) : "l"(a), "l"(b), "l"(c)); return d;
}
static __device__ __forceinline__ u64 mul2(u64 a, u64 b) {
    u64 d; asm("mul.rn.f32x2 %0, %1, %2;" : "=l"(d) : "l"(a), "l"(b)); return d;
}
static __device__ __forceinline__ u64 neg2(u64 a) { return a ^ 0x8000000080000000ULL; }

// ---- fp16 amp pack/unpack (state storage only; math stays fp32) ----
static __device__ __forceinline__ u64 amp_pack(u64 X, u64 Y) {
    float2 x = unpack2(X), y = unpack2(Y);
    __half2 hx = __floats2half2_rn(x.x, x.y);
    __half2 hy = __floats2half2_rn(y.x, y.y);
    unsigned int ix = *reinterpret_cast<unsigned int*>(&hx);
    unsigned int iy = *reinterpret_cast<unsigned int*>(&hy);
    u64 r; asm("mov.b64 %0, {%1, %2};" : "=l"(r) : "r"(ix), "r"(iy));
    return r;
}
static __device__ __forceinline__ void amp_unpack(u64 v, u64& X, u64& Y) {
    unsigned int ix, iy;
    asm("mov.b64 {%0, %1}, %2;" : "=r"(ix), "=r"(iy) : "l"(v));
    float2 x = __half22float2(*reinterpret_cast<__half2*>(&ix));
    float2 y = __half22float2(*reinterpret_cast<__half2*>(&iy));
    X = pack2(x.x, x.y);
    Y = pack2(y.x, y.y);
}

// staircase CNOT permutation on 4 bits (GF2-linear)
__device__ __host__ __forceinline__ constexpr int tau4(int k) {
    int b3 = (k >> 3) & 1;
    int b2 = ((k >> 2) & 1) ^ b3;
    int b1 = ((k >> 1) & 1) ^ b2;
    int b0 = (k & 1) ^ b1;
    return (b3 << 3) | (b2 << 2) | (b1 << 1) | b0;
}

// sw8 images of the k-part for each pass layout (compile-time)
__device__ __host__ __forceinline__ constexpr int offkA(int k) { return (k << 8) ^ k; }
__device__ __host__ __forceinline__ constexpr int offkB(int k) { return (k << 4) ^ k; }
__device__ __host__ __forceinline__ constexpr int offk6(int k) {
    int K = (((k >> 3) & 1) << 8) | (((k >> 2) & 1) << 7)
          | (((k >> 1) & 1) << 4) | ((k & 1) << 3);
    return K ^ ((K >> 4) & 0xF) ^ ((K >> 8) & 0xF);
}

// ---- shared memory layout (bytes) ----
#define SM_ST   0        // u64 st[4096] (fp16x4 amps)     : 32768
#define SM_G    32768    // ulonglong2 gx[3*12] (tn,-tn)   : 576
#define SM_D    33344    // ulonglong2 dtab[2*3*16]        : 1536
#define SM_V    34880    // ulonglong2 v[12][2]            : 384
#define SM_F    35264    // ulonglong2 F[16]               : 256
#define SM_HW   35520    // float hw[12]                   : 48
#define SM_RED  35568    // float2 red[8]                  : 64
#define SM_A3   35632    // float alpha3sq                 : 4
#define SMEM_BYTES 35648

// ---- tangent-form gate bundle ----
struct GX { u64 tn, ntn; };
static __device__ __forceinline__ GX load_gx(const ulonglong2* __restrict__ g) {
    GX r; ulonglong2 p = g[0]; r.tn = p.x; r.ntn = p.y; return r;
}

// tangent-form rotation on pair (i0, i1): 4 FMAs (scale c deferred)
static __device__ __forceinline__ void rxp(const GX& G, u64* X, u64* Y, int i0, int i1) {
    u64 X0 = X[i0], Y0 = Y[i0], X1 = X[i1], Y1 = Y[i1];
    X[i0] = fma2(G.tn, Y1, X0);
    Y[i0] = fma2(G.ntn, X1, Y0);
    X[i1] = fma2(G.tn, Y0, X1);
    Y[i1] = fma2(G.ntn, X0, Y1);
}

// rotation over all 16 regs with pair mask M (each pair once via MSB test)
template<int M, int MSB>
static __device__ __forceinline__ void rotm(const GX& G, u64* X, u64* Y) {
#pragma unroll
    for (int k = 0; k < 16; k++) if (!(k & MSB)) rxp(G, X, Y, k, k ^ M);
}

// apply diagonal entry d to slot k
static __device__ __forceinline__ void diag1e(ulonglong2 d, u64* X, u64* Y, int k) {
    u64 nx = fma2(d.x, X[k], neg2(mul2(d.y, Y[k])));
    u64 ny = fma2(d.x, Y[k], mul2(d.y, X[k]));
    X[k] = nx; Y[k] = ny;
}

// ---- pre-kernel: batch-shared constants, one block ----
__global__ void qsetup_kernel(const float* __restrict__ params,
                              const float* __restrict__ head_w)
{
    int t = threadIdx.x;
    if (t < 36) {                      // tangent coeffs: layer 1+t/12, wire t%12
        float th = params[12 + t];
        float c, s; sincosf(0.5f * th, &s, &c);
        float tn = s / c;
        ulonglong2 e; e.x = dup2(tn); e.y = dup2(-tn);
        g_gx[t] = e;
    }
    if (t == 40) {                     // layer-3 scalar: prod(c)^2
        float prod = 1.f;
#pragma unroll
        for (int w = 0; w < NW; w++) prod *= cosf(0.5f * params[36 + w]);
        g_a3 = prod * prod;
    }
    if (t >= 64 && t < 160) {          // diag tables: prod(c) * e^{i sum th_w bit_w}
        int i = t - 64;                // layer = i/48 (0->L1), window = (i%48)/16, m = i&15
        int l = i / 48, p = (i % 48) / 16, m = i & 15;
        const float* th = params + (l + 1) * NW + 4 * p;
        float phi = 0.f, cprod = 1.f;
#pragma unroll
        for (int q = 0; q < 4; q++) {
            if ((m >> (3 - q)) & 1) phi += th[q];
            cprod *= cosf(0.5f * th[q]);
        }
        float cp, sp; sincosf(phi, &sp, &cp);
        ulonglong2 e; e.x = dup2(cprod * cp); e.y = dup2(cprod * sp);
        g_dtab[i] = e;
    }
    if (t >= 176 && t < 188) {         // layer-0 per-wire param trig
        int w = t - 176;
        float c0, s0; sincosf(0.5f * params[w], &s0, &c0);
        g_l0[w] = make_float4(c0, s0, c0 * c0 - s0 * s0, 2.f * s0 * c0);
    }
}

__global__ void __launch_bounds__(256, 2)
qsim10_kernel(const float* __restrict__ inputs,
              const float* __restrict__ head_w,
              const float* __restrict__ head_b,
              float* __restrict__ out)
{
    extern __shared__ char sm[];
    u64* st          = (u64*)(sm + SM_ST);
    ulonglong2* gx   = (ulonglong2*)(sm + SM_G);
    ulonglong2* dtab = (ulonglong2*)(sm + SM_D);
    ulonglong2* vtab = (ulonglong2*)(sm + SM_V);
    ulonglong2* Ftab = (ulonglong2*)(sm + SM_F);
    float* hw  = (float*)(sm + SM_HW);
    float2* red = (float2*)(sm + SM_RED);
    float* a3  = (float*)(sm + SM_A3);

    const int b = blockIdx.x;
    const int t = threadIdx.x;

    // ---- stage batch-shared constants + per-sample trig ----
    if (t < 36) gx[t] = g_gx[t];
    if (t >= 64 && t < 160) dtab[t - 64] = g_dtab[t - 64];
    if (t == 176) a3[0] = g_a3;
    if (t < NW) {                      // layer-0 per-wire 2-vectors (both samples)
        int w = t;
        float4 l0 = g_l0[w];
        float c0 = l0.x, s0 = l0.y, cn = l0.z, sn = l0.w;
        float v0x[2], v0y[2], v1x[2], v1y[2];
#pragma unroll
        for (int j = 0; j < 2; j++) {
            float cy, sy; sincosf(0.5f * inputs[(2 * b + j) * NW + w], &sy, &cy);
            v0x[j] = c0 * cy;  v0y[j] = -s0 * sy;
            float zx = c0 * sy, zy = -s0 * cy;           // z = -i s cy + c sy
            v1x[j] = cn * zx - sn * zy;                   // e^{i th} * z
            v1y[j] = sn * zx + cn * zy;
        }
        ulonglong2 e0; e0.x = pack2(v0x[0], v0x[1]); e0.y = pack2(v0y[0], v0y[1]);
        ulonglong2 e1; e1.x = pack2(v1x[0], v1x[1]); e1.y = pack2(v1y[0], v1y[1]);
        vtab[(w << 1) | 0] = e0;
        vtab[(w << 1) | 1] = e1;
        hw[w] = head_w[w];
    }
    __syncthreads();

    // ---- F table (wires 0..3 staircase products, per sample-pair) ----
    if (t < 16) {
        int c0 = (t >> 3) & 1, c1 = (t >> 2) & 1, c2 = (t >> 1) & 1, c3 = t & 1;
        int b0 = c0, b1 = c1 ^ c0, b2 = c2 ^ c1, b3 = c3 ^ c2;
        ulonglong2 a = vtab[0 | b0];
        u64 PX = a.x, PY = a.y;
        int bb[3] = {b1, b2, b3};
#pragma unroll
        for (int w = 1; w <= 3; w++) {
            ulonglong2 q = vtab[(w << 1) | bb[w - 1]];
            u64 nx = fma2(PX, q.x, neg2(mul2(PY, q.y)));
            u64 ny = fma2(PX, q.y, mul2(PY, q.x));
            PX = nx; PY = ny;
        }
        ulonglong2 f; f.x = PX; f.y = PY; Ftab[t] = f;
    }

    // ---- per-thread bases under sw8 (a ^ nib1 ^ nib2 folded into low nibble) ----
    const int hi = t >> 4, lo = t & 15;
    const int baseA8  = t ^ hi;                           // res 11-8 (P1, P5)
    const int baseB8  = (hi << 8) | (lo ^ hi);            // res 7-4  (P2, P4)
    const int baseBs8 = baseB8 ^ ((hi & 1) ? 0xFF : 0);   // C34 fold (P2 store)
    const int baseC8  = (t << 4) ^ lo ^ hi;               // res 3-0  (P3)
    // P6 map: amp = t3<<11|t7<<10|t6<<9|k3<<8|k2<<7|t5<<6|t4<<5|k1<<4|k0<<3|t[2:0]
    const int T6 = (((t >> 3) & 1) << 11) | (((t >> 7) & 1) << 10) | (((t >> 6) & 1) << 9)
                 | (((t >> 5) & 1) << 6)  | (((t >> 4) & 1) << 5)  | (t & 7);
    const int base6 = T6 ^ ((T6 >> 4) & 0xF) ^ ((T6 >> 8) & 0xF);
    const int cxC = (t & 1) ? 0xF : 0;                    // C78_l1 in-reg (P3)

    // ---- S^2 measurement weight partials (new P6 wire<->bit sources) ----
    // wires: 0=t3 1=t7 2=t6 3=k3 4=k2 5=t5 6=t4 7=k1 8=k0 9=t2 10=t1 11=t0
    float S0, SA, SB, SC, SD;
    {
        float P08 = (__popc(t & 0x08) & 1) ? -1.f : 1.f;
        float P80 = (__popc(t & 0x80) & 1) ? -1.f : 1.f;
        float P48 = (__popc(t & 0x48) & 1) ? -1.f : 1.f;
        float PA0 = (__popc(t & 0xA0) & 1) ? -1.f : 1.f;
        float P58 = (__popc(t & 0x58) & 1) ? -1.f : 1.f;
        float PA4 = (__popc(t & 0xA4) & 1) ? -1.f : 1.f;
        float PA5 = (__popc(t & 0xA5) & 1) ? -1.f : 1.f;
        float P5A = (__popc(t & 0x5A) & 1) ? -1.f : 1.f;
        S0 = hw[0] * P08 + hw[1] * P80 + hw[2] * P48;     // no k dependence
        SA = hw[3] * P80 + hw[5] * PA0;                   // class k3
        SB = hw[4] * P48 + hw[6] * P58;                   // class k2
        SC = hw[7] * PA0 + hw[9] * PA4 + hw[11] * PA5;    // class k1^k3
        SD = hw[8] * P58 + hw[10] * P5A;                  // class k0^k2
    }
    __syncthreads();

    const ulonglong2* g1 = gx;            // layer-1 tangents (wires 0..11)
    const ulonglong2* g2 = gx + 12;       // layer 2
    const ulonglong2* g3 = gx + 24;       // layer 3 (conjugated rot3~)
    const ulonglong2* d1 = dtab;          // layer-1 diagonals (3 windows x 16)
    const ulonglong2* d2 = dtab + 48;     // layer-2 diagonals

    // ======== P1: init + rot1(w0-3) + diag1 + stair1 store  [res 11-8] ====
    {
        u64 X[16], Y[16];
        int u = t ^ (t >> 1);             // u bit (11-w) = b_w for wires 5..11
        ulonglong2 p5 = vtab[(5 << 1) | ((u >> 6) & 1)];
        u64 PX = p5.x, PY = p5.y;
#pragma unroll
        for (int w = 6; w <= 11; w++) {
            ulonglong2 q = vtab[(w << 1) | ((u >> (11 - w)) & 1)];
            u64 nx = fma2(PX, q.x, neg2(mul2(PY, q.y)));
            u64 ny = fma2(PX, q.y, mul2(PY, q.x));
            PX = nx; PY = ny;
        }
        int t7 = (t >> 7) & 1;
        ulonglong2 q0 = vtab[(4 << 1) | t7];
        ulonglong2 q1 = vtab[(4 << 1) | (t7 ^ 1)];
        u64 R0X = fma2(PX, q0.x, neg2(mul2(PY, q0.y)));
        u64 R0Y = fma2(PX, q0.y, mul2(PY, q0.x));
        u64 R1X = fma2(PX, q1.x, neg2(mul2(PY, q1.y)));
        u64 R1Y = fma2(PX, q1.y, mul2(PY, q1.x));
        GX G0 = load_gx(g1);
#pragma unroll
        for (int j = 0; j < 8; j++) {     // build pair (j, j|8), rotate wire0
            ulonglong2 Fk0 = Ftab[j];
            u64 QX = (j & 1) ? R1X : R0X;
            u64 QY = (j & 1) ? R1Y : R0Y;
            X[j] = fma2(Fk0.x, QX, neg2(mul2(Fk0.y, QY)));
            Y[j] = fma2(Fk0.x, QY, mul2(Fk0.y, QX));
            ulonglong2 Fk1 = Ftab[j | 8];
            X[j | 8] = fma2(Fk1.x, QX, neg2(mul2(Fk1.y, QY)));
            Y[j | 8] = fma2(Fk1.x, QY, mul2(Fk1.y, QX));
            rxp(G0, X, Y, j, j | 8);
        }
        GX G1 = load_gx(g1 + 1); rotm<4, 4>(G1, X, Y);
        GX G2 = load_gx(g1 + 2); rotm<2, 2>(G2, X, Y);
        GX G3 = load_gx(g1 + 3); rotm<1, 1>(G3, X, Y);
#pragma unroll
        for (int k = 0; k < 16; k++) {    // diag1(A) + stair1 store
            diag1e(d1[k], X, Y, k);
            st[baseA8 ^ offkA(tau4(k))] = amp_pack(X[k], Y[k]);
        }
    }
    __syncthreads();

    // ======== P2: rot1(w4-7) + diag1 + stair1 + C34 fold  [res 7-4] ====
    {
        u64 X[16], Y[16];
        GX G4 = load_gx(g1 + 4);
#pragma unroll
        for (int j = 0; j < 8; j++) {
            amp_unpack(st[baseB8 ^ offkB(j)],     X[j],     Y[j]);
            amp_unpack(st[baseB8 ^ offkB(j | 8)], X[j | 8], Y[j | 8]);
            rxp(G4, X, Y, j, j | 8);
        }
        GX G5 = load_gx(g1 + 5); rotm<4, 4>(G5, X, Y);
        GX G6 = load_gx(g1 + 6); rotm<2, 2>(G6, X, Y);
        GX G7 = load_gx(g1 + 7); rotm<1, 1>(G7, X, Y);
#pragma unroll
        for (int k = 0; k < 16; k++) {
            diag1e(d1[16 + k], X, Y, k);
            st[baseBs8 ^ offkB(tau4(k))] = amp_pack(X[k], Y[k]);
        }
    }
    __syncthreads();

    // ======== P3: rot1(w8-11)+diag1+stair1+C78(in-reg)+rot2+diag2+rot3~ ====
    {
        u64 X[16], Y[16];
        GX G8 = load_gx(g1 + 8);
#pragma unroll
        for (int j = 0; j < 8; j++) {
            amp_unpack(st[baseC8 ^ j],       X[j],     Y[j]);
            amp_unpack(st[baseC8 ^ (j | 8)], X[j | 8], Y[j | 8]);
            rxp(G8, X, Y, j, j | 8);
        }
        GX G9  = load_gx(g1 + 9);  rotm<4, 4>(G9, X, Y);
        GX G10 = load_gx(g1 + 10); rotm<2, 2>(G10, X, Y);
        GX G11 = load_gx(g1 + 11); rotm<1, 1>(G11, X, Y);
#pragma unroll
        for (int k = 0; k < 16; k++) diag1e(d1[32 + k], X, Y, k);  // diag1(C)
        // rot2(w8-11) in final-label space: offsets tau4^-1(8,4,2,1)=12,6,3,1
        GX H8  = load_gx(g2 + 8);  rotm<12, 8>(H8, X, Y);
        GX H9  = load_gx(g2 + 9);  rotm<6, 4>(H9, X, Y);
        GX H10 = load_gx(g2 + 10); rotm<3, 2>(H10, X, Y);
        GX H11 = load_gx(g2 + 11); rotm<1, 1>(H11, X, Y);
#pragma unroll
        for (int k = 0; k < 16; k++) diag1e(d2[32 + (tau4(k) ^ cxC)], X, Y, k);
        // rot3~(w8..11): final masks {3,2},{2,1},{1,0},{0} -> orig 0xA,5,2,1
        GX J8  = load_gx(g3 + 8);  rotm<10, 8>(J8, X, Y);
        GX J9  = load_gx(g3 + 9);  rotm<5, 4>(J9, X, Y);
        GX J10 = load_gx(g3 + 10); rotm<2, 2>(J10, X, Y);
        GX J11 = load_gx(g3 + 11); rotm<1, 1>(J11, X, Y);
#pragma unroll
        for (int k = 0; k < 16; k++)
            st[baseC8 ^ tau4(k)] = amp_pack(X[k], Y[k]);
    }
    __syncthreads();

    // ======== P4: rot2(w4-7)+diag2+rot3~(w4-6)  [res 7-4] ====
    // load corrects P3's residual: true amp bits3-0 ^= 0xF when bit4(=k0)=1
    {
        u64 X[16], Y[16];
        GX H4 = load_gx(g2 + 4);
#pragma unroll
        for (int j = 0; j < 8; j++) {
            int fx = (j & 1) ? 0xF : 0;
            amp_unpack(st[baseB8 ^ offkB(j) ^ fx],       X[j],     Y[j]);
            amp_unpack(st[baseB8 ^ offkB(j | 8) ^ fx],   X[j | 8], Y[j | 8]);
            rxp(H4, X, Y, j, j | 8);
        }
        GX H5 = load_gx(g2 + 5); rotm<4, 4>(H5, X, Y);
        GX H6 = load_gx(g2 + 6); rotm<2, 2>(H6, X, Y);
        GX H7 = load_gx(g2 + 7); rotm<1, 1>(H7, X, Y);
#pragma unroll
        for (int k = 0; k < 16; k++) diag1e(d2[16 + k], X, Y, k);
        GX J4 = load_gx(g3 + 4); rotm<12, 8>(J4, X, Y);   // w4: bits{7,6}
        GX J5 = load_gx(g3 + 5); rotm<6, 4>(J5, X, Y);    // w5: bits{6,5}
        GX J6 = load_gx(g3 + 6); rotm<3, 2>(J6, X, Y);    // w6: bits{5,4}
#pragma unroll
        for (int k = 0; k < 16; k++)
            st[baseB8 ^ offkB(k)] = amp_pack(X[k], Y[k]); // canonical store
    }
    __syncthreads();

    // ======== P5: rot2(w0-3)+diag2+rot3~(w0-2)  [res 11-8] ====
    {
        u64 X[16], Y[16];
        GX H0 = load_gx(g2);
#pragma unroll
        for (int j = 0; j < 8; j++) {
            amp_unpack(st[baseA8 ^ offkA(j)],       X[j],     Y[j]);
            amp_unpack(st[baseA8 ^ offkA(j | 8)],   X[j | 8], Y[j | 8]);
            rxp(H0, X, Y, j, j | 8);
        }
        GX H1 = load_gx(g2 + 1); rotm<4, 4>(H1, X, Y);
        GX H2 = load_gx(g2 + 2); rotm<2, 2>(H2, X, Y);
        GX H3 = load_gx(g2 + 3); rotm<1, 1>(H3, X, Y);
#pragma unroll
        for (int k = 0; k < 16; k++) diag1e(d2[k], X, Y, k);
        GX J0 = load_gx(g3);     rotm<12, 8>(J0, X, Y);   // w0: bits{11,10}
        GX J1 = load_gx(g3 + 1); rotm<6, 4>(J1, X, Y);    // w1: bits{10,9}
        GX J2 = load_gx(g3 + 2); rotm<3, 2>(J2, X, Y);    // w2: bits{9,8}
#pragma unroll
        for (int k = 0; k < 16; k++)
            st[baseA8 ^ offkA(k)] = amp_pack(X[k], Y[k]);
    }
    __syncthreads();

    // ======== P6: rot3~(w3), rot3~(w7) + fused measurement  [res 8,7,4,3] ====
    float pacc[2] = {0.f, 0.f};
    {
        u64 X[16], Y[16];
#pragma unroll
        for (int k = 0; k < 16; k++)
            amp_unpack(st[base6 ^ offk6(k)], X[k], Y[k]);
        GX J3 = load_gx(g3 + 3); rotm<12, 8>(J3, X, Y);   // w3: bits{8,7}=k3,k2
        GX J7 = load_gx(g3 + 7); rotm<3, 2>(J7, X, Y);    // w7: bits{4,3}=k1,k0
#pragma unroll
        for (int k = 0; k < 16; k++) {
            float wl = S0
                + (((k >> 3) & 1) ? -SA : SA)
                + (((k >> 2) & 1) ? -SB : SB)
                + ((((k >> 1) ^ (k >> 3)) & 1) ? -SC : SC)
                + (((k ^ (k >> 2)) & 1) ? -SD : SD);
            u64 U = fma2(X[k], X[k], mul2(Y[k], Y[k]));
            float2 u = unpack2(U);
            pacc[0] = fmaf(u.x, wl, pacc[0]);
            pacc[1] = fmaf(u.y, wl, pacc[1]);
        }
    }

    // ---- reduce both samples; apply deferred layer-3 scale ----
    float p0 = pacc[0], p1 = pacc[1];
#pragma unroll
    for (int o = 16; o; o >>= 1) {
        p0 += __shfl_xor_sync(0xFFFFFFFFu, p0, o);
        p1 += __shfl_xor_sync(0xFFFFFFFFu, p1, o);
    }
    if ((t & 31) == 0) red[t >> 5] = make_float2(p0, p1);
    __syncthreads();
    if (t < 2) {
        float s = 0.f;
#pragma unroll
        for (int w = 0; w < 8; w++) s += (t == 0) ? red[w].x : red[w].y;
        out[2 * b + t] = s * a3[0] + head_b[0];
    }
}

extern "C" void kernel_launch(void* const* d_in, const int* in_sizes, int n_in,
                              void* d_out, int out_size)
{
    const float* inputs = (const float*)d_in[0];
    const float* params = (const float*)d_in[1];
    const float* head_w = (const float*)d_in[2];
    const float* head_b = (const float*)d_in[3];
    float* out = (float*)d_out;

    cudaFuncSetAttribute(qsim10_kernel, cudaFuncAttributeMaxDynamicSharedMemorySize, SMEM_BYTES);
    qsetup_kernel<<<1, 192>>>(params, head_w);           // batch-shared constants
    int B2 = out_size / 2;                               // two samples per block
    qsim10_kernel<<<B2, 256, SMEM_BYTES>>>(inputs, head_w, head_b, out);
}

// round 15
// speedup vs baseline: 1.4108x; 1.0019x over previous
#include <cuda_runtime.h>
#include <cuda_fp16.h>

// QuantumRegression: 12-wire state-vector sim, two samples per block packed
// into f32x2 lanes. Registers/math are fp32 (f32x2); the SHARED state is
// stored fp16: one u64 per amp = (X half2, Y half2) = 8 bytes (was 16).
// Storage index sw8(a) = a ^ ((a>>4)&0xF) ^ ((a>>8)&0xF) -- both upper
// nibbles folded into the low nibble; verified conflict-free for every pass
// layout at LDS.64 16-lane phase granularity.
//
// SIX-PASS schedule via CNOT-chain conjugation (algebra identical to R13):
//  - Layer 0 folded into closed-form product-state init (prefix parity).
//  - stair2/stair3 deferred into measurement weights (S^2 parity sets).
//  - Layer-3 RX conjugated through stair2: rot3~(w) = exp(-i th/2 X_w X_{w+1}).
//  - P1: init + rot1(w0-3)+diag1+stair1 store            [res bits 11-8]
//  - P2: rot1(w4-7)+diag1+stair1+C34 store fold           [res bits 7-4]
//  - P3: rot1(w8-11)+diag1+stair1+C78(in-reg)+rot2(w8-11)
//        +diag2+rot3~(w8-11); residual folded into P4 load [res bits 3-0]
//  - P4: rot2(w4-7)+diag2+rot3~(w4-6)                     [res bits 7-4]
//  - P5: rot2(w0-3)+diag2+rot3~(w0-2)                     [res bits 11-8]
//  - P6: rot3~(w3),rot3~(w7) + fused S^2 measurement      [res bits 8,7,4,3]
//    P6 t-bit map re-chosen (t3 at amp bit 11) so sw8 keeps the low nibble
//    injective; S-masks re-derived for the new wire<->bit sources.
//  Tangent-form rotations; dropped cosines -> diag tables / alpha3^2 scalar.

typedef unsigned long long u64;

#define NW 12

// ---- batch-shared constant staging (written by qsetup_kernel) ----
__device__ ulonglong2 g_gx[36];      // tangent gates (tn, -tn) layers 1..3
__device__ ulonglong2 g_dtab[96];    // diag*prod(c) tables, layers 1..2
__device__ float      g_a3;          // layer-3 prod(c)^2
__device__ float4     g_l0[12];      // per-wire layer-0: c0, s0, cos(th), sin(th)

// ---- packed f32x2 helpers ----
static __device__ __forceinline__ u64 pack2(float lo, float hi) {
    u64 r; asm("mov.b64 %0, {%1, %2};" : "=l"(r) : "f"(lo), "f"(hi)); return r;
}
static __device__ __forceinline__ float2 unpack2(u64 v) {
    float2 r; asm("mov.b64 {%0, %1}, %2;" : "=f"(r.x), "=f"(r.y) : "l"(v)); return r;
}
static __device__ __forceinline__ u64 dup2(float v) { return pack2(v, v); }
static __device__ __forceinline__ u64 fma2(u64 a, u64 b, u64 c) {
    u64 d; asm("fma.rn.f32x2 %0, %1, %2, %3;" : "=l"(d) : "l"(a), "l"(b), "l"(c)); return d;
}
static __device__ __forceinline__ u64 mul2(u64 a, u64 b) {
    u64 d; asm("mul.rn.f32x2 %0, %1, %2;" : "=l"(d) : "l"(a), "l"(b)); return d;
}
static __device__ __forceinline__ u64 neg2(u64 a) { return a ^ 0x8000000080000000ULL; }

// ---- fp16 amp pack/unpack (state storage only; math stays fp32) ----
static __device__ __forceinline__ u64 amp_pack(u64 X, u64 Y) {
    float2 x = unpack2(X), y = unpack2(Y);
    __half2 hx = __floats2half2_rn(x.x, x.y);
    __half2 hy = __floats2half2_rn(y.x, y.y);
    unsigned int ix = *reinterpret_cast<unsigned int*>(&hx);
    unsigned int iy = *reinterpret_cast<unsigned int*>(&hy);
    u64 r; asm("mov.b64 %0, {%1, %2};" : "=l"(r) : "r"(ix), "r"(iy));
    return r;
}
static __device__ __forceinline__ void amp_unpack(u64 v, u64& X, u64& Y) {
    unsigned int ix, iy;
    asm("mov.b64 {%0, %1}, %2;" : "=r"(ix), "=r"(iy) : "l"(v));
    float2 x = __half22float2(*reinterpret_cast<__half2*>(&ix));
    float2 y = __half22float2(*reinterpret_cast<__half2*>(&iy));
    X = pack2(x.x, x.y);
    Y = pack2(y.x, y.y);
}

// staircase CNOT permutation on 4 bits (GF2-linear)
__device__ __host__ __forceinline__ constexpr int tau4(int k) {
    int b3 = (k >> 3) & 1;
    int b2 = ((k >> 2) & 1) ^ b3;
    int b1 = ((k >> 1) & 1) ^ b2;
    int b0 = (k & 1) ^ b1;
    return (b3 << 3) | (b2 << 2) | (b1 << 1) | b0;
}

// sw8 images of the k-part for each pass layout (compile-time)
__device__ __host__ __forceinline__ constexpr int offkA(int k) { return (k << 8) ^ k; }
__device__ __host__ __forceinline__ constexpr int offkB(int k) { return (k << 4) ^ k; }
__device__ __host__ __forceinline__ constexpr int offk6(int k) {
    int K = (((k >> 3) & 1) << 8) | (((k >> 2) & 1) << 7)
          | (((k >> 1) & 1) << 4) | ((k & 1) << 3);
    return K ^ ((K >> 4) & 0xF) ^ ((K >> 8) & 0xF);
}

// ---- shared memory layout (bytes) ----
#define SM_ST   0        // u64 st[4096] (fp16x4 amps)     : 32768
#define SM_G    32768    // ulonglong2 gx[3*12] (tn,-tn)   : 576
#define SM_D    33344    // ulonglong2 dtab[2*3*16]        : 1536
#define SM_V    34880    // ulonglong2 v[12][2]            : 384
#define SM_F    35264    // ulonglong2 F[16]               : 256
#define SM_HW   35520    // float hw[12]                   : 48
#define SM_RED  35568    // float2 red[8]                  : 64
#define SM_A3   35632    // float alpha3sq                 : 4
#define SMEM_BYTES 35648

// ---- tangent-form gate bundle ----
struct GX { u64 tn, ntn; };
static __device__ __forceinline__ GX load_gx(const ulonglong2* __restrict__ g) {
    GX r; ulonglong2 p = g[0]; r.tn = p.x; r.ntn = p.y; return r;
}

// tangent-form rotation on pair (i0, i1): 4 FMAs (scale c deferred)
static __device__ __forceinline__ void rxp(const GX& G, u64* X, u64* Y, int i0, int i1) {
    u64 X0 = X[i0], Y0 = Y[i0], X1 = X[i1], Y1 = Y[i1];
    X[i0] = fma2(G.tn, Y1, X0);
    Y[i0] = fma2(G.ntn, X1, Y0);
    X[i1] = fma2(G.tn, Y0, X1);
    Y[i1] = fma2(G.ntn, X0, Y1);
}

// rotation over all 16 regs with pair mask M (each pair once via MSB test)
template<int M, int MSB>
static __device__ __forceinline__ void rotm(const GX& G, u64* X, u64* Y) {
#pragma unroll
    for (int k = 0; k < 16; k++) if (!(k & MSB)) rxp(G, X, Y, k, k ^ M);
}

// apply diagonal entry d to slot k
static __device__ __forceinline__ void diag1e(ulonglong2 d, u64* X, u64* Y, int k) {
    u64 nx = fma2(d.x, X[k], neg2(mul2(d.y, Y[k])));
    u64 ny = fma2(d.x, Y[k], mul2(d.y, X[k]));
    X[k] = nx; Y[k] = ny;
}

// ---- pre-kernel: batch-shared constants, one block ----
__global__ void qsetup_kernel(const float* __restrict__ params,
                              const float* __restrict__ head_w)
{
    int t = threadIdx.x;
    if (t < 36) {                      // tangent coeffs: layer 1+t/12, wire t%12
        float th = params[12 + t];
        float c, s; sincosf(0.5f * th, &s, &c);
        float tn = s / c;
        ulonglong2 e; e.x = dup2(tn); e.y = dup2(-tn);
        g_gx[t] = e;
    }
    if (t == 40) {                     // layer-3 scalar: prod(c)^2
        float prod = 1.f;
#pragma unroll
        for (int w = 0; w < NW; w++) prod *= cosf(0.5f * params[36 + w]);
        g_a3 = prod * prod;
    }
    if (t >= 64 && t < 160) {          // diag tables: prod(c) * e^{i sum th_w bit_w}
        int i = t - 64;                // layer = i/48 (0->L1), window = (i%48)/16, m = i&15
        int l = i / 48, p = (i % 48) / 16, m = i & 15;
        const float* th = params + (l + 1) * NW + 4 * p;
        float phi = 0.f, cprod = 1.f;
#pragma unroll
        for (int q = 0; q < 4; q++) {
            if ((m >> (3 - q)) & 1) phi += th[q];
            cprod *= cosf(0.5f * th[q]);
        }
        float cp, sp; sincosf(phi, &sp, &cp);
        ulonglong2 e; e.x = dup2(cprod * cp); e.y = dup2(cprod * sp);
        g_dtab[i] = e;
    }
    if (t >= 176 && t < 188) {         // layer-0 per-wire param trig
        int w = t - 176;
        float c0, s0; sincosf(0.5f * params[w], &s0, &c0);
        g_l0[w] = make_float4(c0, s0, c0 * c0 - s0 * s0, 2.f * s0 * c0);
    }
}

__global__ void __launch_bounds__(256, 2)
qsim10_kernel(const float* __restrict__ inputs,
              const float* __restrict__ head_w,
              const float* __restrict__ head_b,
              float* __restrict__ out)
{
    extern __shared__ char sm[];
    u64* st          = (u64*)(sm + SM_ST);
    ulonglong2* gx   = (ulonglong2*)(sm + SM_G);
    ulonglong2* dtab = (ulonglong2*)(sm + SM_D);
    ulonglong2* vtab = (ulonglong2*)(sm + SM_V);
    ulonglong2* Ftab = (ulonglong2*)(sm + SM_F);
    float* hw  = (float*)(sm + SM_HW);
    float2* red = (float2*)(sm + SM_RED);
    float* a3  = (float*)(sm + SM_A3);

    const int b = blockIdx.x;
    const int t = threadIdx.x;

    // ---- stage batch-shared constants + per-sample trig ----
    if (t < 36) gx[t] = g_gx[t];
    if (t >= 64 && t < 160) dtab[t - 64] = g_dtab[t - 64];
    if (t == 176) a3[0] = g_a3;
    if (t < NW) {                      // layer-0 per-wire 2-vectors (both samples)
        int w = t;
        float4 l0 = g_l0[w];
        float c0 = l0.x, s0 = l0.y, cn = l0.z, sn = l0.w;
        float v0x[2], v0y[2], v1x[2], v1y[2];
#pragma unroll
        for (int j = 0; j < 2; j++) {
            float cy, sy; sincosf(0.5f * inputs[(2 * b + j) * NW + w], &sy, &cy);
            v0x[j] = c0 * cy;  v0y[j] = -s0 * sy;
            float zx = c0 * sy, zy = -s0 * cy;           // z = -i s cy + c sy
            v1x[j] = cn * zx - sn * zy;                   // e^{i th} * z
            v1y[j] = sn * zx + cn * zy;
        }
        ulonglong2 e0; e0.x = pack2(v0x[0], v0x[1]); e0.y = pack2(v0y[0], v0y[1]);
        ulonglong2 e1; e1.x = pack2(v1x[0], v1x[1]); e1.y = pack2(v1y[0], v1y[1]);
        vtab[(w << 1) | 0] = e0;
        vtab[(w << 1) | 1] = e1;
        hw[w] = head_w[w];
    }
    __syncthreads();

    // ---- F table (wires 0..3 staircase products, per sample-pair) ----
    if (t < 16) {
        int c0 = (t >> 3) & 1, c1 = (t >> 2) & 1, c2 = (t >> 1) & 1, c3 = t & 1;
        int b0 = c0, b1 = c1 ^ c0, b2 = c2 ^ c1, b3 = c3 ^ c2;
        ulonglong2 a = vtab[0 | b0];
        u64 PX = a.x, PY = a.y;
        int bb[3] = {b1, b2, b3};
#pragma unroll
        for (int w = 1; w <= 3; w++) {
            ulonglong2 q = vtab[(w << 1) | bb[w - 1]];
            u64 nx = fma2(PX, q.x, neg2(mul2(PY, q.y)));
            u64 ny = fma2(PX, q.y, mul2(PY, q.x));
            PX = nx; PY = ny;
        }
        ulonglong2 f; f.x = PX; f.y = PY; Ftab[t] = f;
    }

    // ---- per-thread bases under sw8 (a ^ nib1 ^ nib2 folded into low nibble) ----
    const int hi = t >> 4, lo = t & 15;
    const int baseA8  = t ^ hi;                           // res 11-8 (P1, P5)
    const int baseB8  = (hi << 8) | (lo ^ hi);            // res 7-4  (P2, P4)
    const int baseBs8 = baseB8 ^ ((hi & 1) ? 0xFF : 0);   // C34 fold (P2 store)
    const int baseC8  = (t << 4) ^ lo ^ hi;               // res 3-0  (P3)
    // P6 map: amp = t3<<11|t7<<10|t6<<9|k3<<8|k2<<7|t5<<6|t4<<5|k1<<4|k0<<3|t[2:0]
    const int T6 = (((t >> 3) & 1) << 11) | (((t >> 7) & 1) << 10) | (((t >> 6) & 1) << 9)
                 | (((t >> 5) & 1) << 6)  | (((t >> 4) & 1) << 5)  | (t & 7);
    const int base6 = T6 ^ ((T6 >> 4) & 0xF) ^ ((T6 >> 8) & 0xF);
    const int cxC = (t & 1) ? 0xF : 0;                    // C78_l1 in-reg (P3)

    // ---- S^2 measurement weight partials (new P6 wire<->bit sources) ----
    // wires: 0=t3 1=t7 2=t6 3=k3 4=k2 5=t5 6=t4 7=k1 8=k0 9=t2 10=t1 11=t0
    float S0, SA, SB, SC, SD;
    {
        float P08 = (__popc(t & 0x08) & 1) ? -1.f : 1.f;
        float P80 = (__popc(t & 0x80) & 1) ? -1.f : 1.f;
        float P48 = (__popc(t & 0x48) & 1) ? -1.f : 1.f;
        float PA0 = (__popc(t & 0xA0) & 1) ? -1.f : 1.f;
        float P58 = (__popc(t & 0x58) & 1) ? -1.f : 1.f;
        float PA4 = (__popc(t & 0xA4) & 1) ? -1.f : 1.f;
        float PA5 = (__popc(t & 0xA5) & 1) ? -1.f : 1.f;
        float P5A = (__popc(t & 0x5A) & 1) ? -1.f : 1.f;
        S0 = hw[0] * P08 + hw[1] * P80 + hw[2] * P48;     // no k dependence
        SA = hw[3] * P80 + hw[5] * PA0;                   // class k3
        SB = hw[4] * P48 + hw[6] * P58;                   // class k2
        SC = hw[7] * PA0 + hw[9] * PA4 + hw[11] * PA5;    // class k1^k3
        SD = hw[8] * P58 + hw[10] * P5A;                  // class k0^k2
    }
    __syncthreads();

    const ulonglong2* g1 = gx;            // layer-1 tangents (wires 0..11)
    const ulonglong2* g2 = gx + 12;       // layer 2
    const ulonglong2* g3 = gx + 24;       // layer 3 (conjugated rot3~)
    const ulonglong2* d1 = dtab;          // layer-1 diagonals (3 windows x 16)
    const ulonglong2* d2 = dtab + 48;     // layer-2 diagonals

    // ======== P1: init + rot1(w0-3) + diag1 + stair1 store  [res 11-8] ====
    {
        u64 X[16], Y[16];
        int u = t ^ (t >> 1);             // u bit (11-w) = b_w for wires 5..11
        ulonglong2 p5 = vtab[(5 << 1) | ((u >> 6) & 1)];
        u64 PX = p5.x, PY = p5.y;
#pragma unroll
        for (int w = 6; w <= 11; w++) {
            ulonglong2 q = vtab[(w << 1) | ((u >> (11 - w)) & 1)];
            u64 nx = fma2(PX, q.x, neg2(mul2(PY, q.y)));
            u64 ny = fma2(PX, q.y, mul2(PY, q.x));
            PX = nx; PY = ny;
        }
        int t7 = (t >> 7) & 1;
        ulonglong2 q0 = vtab[(4 << 1) | t7];
        ulonglong2 q1 = vtab[(4 << 1) | (t7 ^ 1)];
        u64 R0X = fma2(PX, q0.x, neg2(mul2(PY, q0.y)));
        u64 R0Y = fma2(PX, q0.y, mul2(PY, q0.x));
        u64 R1X = fma2(PX, q1.x, neg2(mul2(PY, q1.y)));
        u64 R1Y = fma2(PX, q1.y, mul2(PY, q1.x));
        GX G0 = load_gx(g1);
#pragma unroll
        for (int j = 0; j < 8; j++) {     // build pair (j, j|8), rotate wire0
            ulonglong2 Fk0 = Ftab[j];
            u64 QX = (j & 1) ? R1X : R0X;
            u64 QY = (j & 1) ? R1Y : R0Y;
            X[j] = fma2(Fk0.x, QX, neg2(mul2(Fk0.y, QY)));
            Y[j] = fma2(Fk0.x, QY, mul2(Fk0.y, QX));
            ulonglong2 Fk1 = Ftab[j | 8];
            X[j | 8] = fma2(Fk1.x, QX, neg2(mul2(Fk1.y, QY)));
            Y[j | 8] = fma2(Fk1.x, QY, mul2(Fk1.y, QX));
            rxp(G0, X, Y, j, j | 8);
        }
        GX G1 = load_gx(g1 + 1); rotm<4, 4>(G1, X, Y);
        GX G2 = load_gx(g1 + 2); rotm<2, 2>(G2, X, Y);
        GX G3 = load_gx(g1 + 3); rotm<1, 1>(G3, X, Y);
#pragma unroll
        for (int k = 0; k < 16; k++) {    // diag1(A) + stair1 store
            diag1e(d1[k], X, Y, k);
            st[baseA8 ^ offkA(tau4(k))] = amp_pack(X[k], Y[k]);
        }
    }
    __syncthreads();

    // ======== P2: rot1(w4-7) + diag1 + stair1 + C34 fold  [res 7-4] ====
    {
        u64 X[16], Y[16];
        GX G4 = load_gx(g1 + 4);
#pragma unroll
        for (int j = 0; j < 8; j++) {
            amp_unpack(st[baseB8 ^ offkB(j)],     X[j],     Y[j]);
            amp_unpack(st[baseB8 ^ offkB(j | 8)], X[j | 8], Y[j | 8]);
            rxp(G4, X, Y, j, j | 8);
        }
        GX G5 = load_gx(g1 + 5); rotm<4, 4>(G5, X, Y);
        GX G6 = load_gx(g1 + 6); rotm<2, 2>(G6, X, Y);
        GX G7 = load_gx(g1 + 7); rotm<1, 1>(G7, X, Y);
#pragma unroll
        for (int k = 0; k < 16; k++) {
            diag1e(d1[16 + k], X, Y, k);
            st[baseBs8 ^ offkB(tau4(k))] = amp_pack(X[k], Y[k]);
        }
    }
    __syncthreads();

    // ======== P3: rot1(w8-11)+diag1+stair1+C78(in-reg)+rot2+diag2+rot3~ ====
    {
        u64 X[16], Y[16];
        GX G8 = load_gx(g1 + 8);
#pragma unroll
        for (int j = 0; j < 8; j++) {
            amp_unpack(st[baseC8 ^ j],       X[j],     Y[j]);
            amp_unpack(st[baseC8 ^ (j | 8)], X[j | 8], Y[j | 8]);
            rxp(G8, X, Y, j, j | 8);
        }
        GX G9  = load_gx(g1 + 9);  rotm<4, 4>(G9, X, Y);
        GX G10 = load_gx(g1 + 10); rotm<2, 2>(G10, X, Y);
        GX G11 = load_gx(g1 + 11); rotm<1, 1>(G11, X, Y);
#pragma unroll
        for (int k = 0; k < 16; k++) diag1e(d1[32 + k], X, Y, k);  // diag1(C)
        // rot2(w8-11) in final-label space: offsets tau4^-1(8,4,2,1)=12,6,3,1
        GX H8  = load_gx(g2 + 8);  rotm<12, 8>(H8, X, Y);
        GX H9  = load_gx(g2 + 9);  rotm<6, 4>(H9, X, Y);
        GX H10 = load_gx(g2 + 10); rotm<3, 2>(H10, X, Y);
        GX H11 = load_gx(g2 + 11); rotm<1, 1>(H11, X, Y);
#pragma unroll
        for (int k = 0; k < 16; k++) diag1e(d2[32 + (tau4(k) ^ cxC)], X, Y, k);
        // rot3~(w8..11): final masks {3,2},{2,1},{1,0},{0} -> orig 0xA,5,2,1
        GX J8  = load_gx(g3 + 8);  rotm<10, 8>(J8, X, Y);
        GX J9  = load_gx(g3 + 9);  rotm<5, 4>(J9, X, Y);
        GX J10 = load_gx(g3 + 10); rotm<2, 2>(J10, X, Y);
        GX J11 = load_gx(g3 + 11); rotm<1, 1>(J11, X, Y);
#pragma unroll
        for (int k = 0; k < 16; k++)
            st[baseC8 ^ tau4(k)] = amp_pack(X[k], Y[k]);
    }
    __syncthreads();

    // ======== P4: rot2(w4-7)+diag2+rot3~(w4-6)  [res 7-4] ====
    // load corrects P3's residual: true amp bits3-0 ^= 0xF when bit4(=k0)=1
    {
        u64 X[16], Y[16];
        GX H4 = load_gx(g2 + 4);
#pragma unroll
        for (int j = 0; j < 8; j++) {
            int fx = (j & 1) ? 0xF : 0;
            amp_unpack(st[baseB8 ^ offkB(j) ^ fx],       X[j],     Y[j]);
            amp_unpack(st[baseB8 ^ offkB(j | 8) ^ fx],   X[j | 8], Y[j | 8]);
            rxp(H4, X, Y, j, j | 8);
        }
        GX H5 = load_gx(g2 + 5); rotm<4, 4>(H5, X, Y);
        GX H6 = load_gx(g2 + 6); rotm<2, 2>(H6, X, Y);
        GX H7 = load_gx(g2 + 7); rotm<1, 1>(H7, X, Y);
#pragma unroll
        for (int k = 0; k < 16; k++) diag1e(d2[16 + k], X, Y, k);
        GX J4 = load_gx(g3 + 4); rotm<12, 8>(J4, X, Y);   // w4: bits{7,6}
        GX J5 = load_gx(g3 + 5); rotm<6, 4>(J5, X, Y);    // w5: bits{6,5}
        GX J6 = load_gx(g3 + 6); rotm<3, 2>(J6, X, Y);    // w6: bits{5,4}
#pragma unroll
        for (int k = 0; k < 16; k++)
            st[baseB8 ^ offkB(k)] = amp_pack(X[k], Y[k]); // canonical store
    }
    __syncthreads();

    // ======== P5: rot2(w0-3)+diag2+rot3~(w0-2)  [res 11-8] ====
    {
        u64 X[16], Y[16];
        GX H0 = load_gx(g2);
#pragma unroll
        for (int j = 0; j < 8; j++) {
            amp_unpack(st[baseA8 ^ offkA(j)],       X[j],     Y[j]);
            amp_unpack(st[baseA8 ^ offkA(j | 8)],   X[j | 8], Y[j | 8]);
            rxp(H0, X, Y, j, j | 8);
        }
        GX H1 = load_gx(g2 + 1); rotm<4, 4>(H1, X, Y);
        GX H2 = load_gx(g2 + 2); rotm<2, 2>(H2, X, Y);
        GX H3 = load_gx(g2 + 3); rotm<1, 1>(H3, X, Y);
#pragma unroll
        for (int k = 0; k < 16; k++) diag1e(d2[k], X, Y, k);
        GX J0 = load_gx(g3);     rotm<12, 8>(J0, X, Y);   // w0: bits{11,10}
        GX J1 = load_gx(g3 + 1); rotm<6, 4>(J1, X, Y);    // w1: bits{10,9}
        GX J2 = load_gx(g3 + 2); rotm<3, 2>(J2, X, Y);    // w2: bits{9,8}
#pragma unroll
        for (int k = 0; k < 16; k++)
            st[baseA8 ^ offkA(k)] = amp_pack(X[k], Y[k]);
    }
    __syncthreads();

    // ======== P6: rot3~(w3), rot3~(w7) + fused measurement  [res 8,7,4,3] ====
    float pacc[2] = {0.f, 0.f};
    {
        u64 X[16], Y[16];
#pragma unroll
        for (int k = 0; k < 16; k++)
            amp_unpack(st[base6 ^ offk6(k)], X[k], Y[k]);
        GX J3 = load_gx(g3 + 3); rotm<12, 8>(J3, X, Y);   // w3: bits{8,7}=k3,k2
        GX J7 = load_gx(g3 + 7); rotm<3, 2>(J7, X, Y);    // w7: bits{4,3}=k1,k0
#pragma unroll
        for (int k = 0; k < 16; k++) {
            float wl = S0
                + (((k >> 3) & 1) ? -SA : SA)
                + (((k >> 2) & 1) ? -SB : SB)
                + ((((k >> 1) ^ (k >> 3)) & 1) ? -SC : SC)
                + (((k ^ (k >> 2)) & 1) ? -SD : SD);
            u64 U = fma2(X[k], X[k], mul2(Y[k], Y[k]));
            float2 u = unpack2(U);
            pacc[0] = fmaf(u.x, wl, pacc[0]);
            pacc[1] = fmaf(u.y, wl, pacc[1]);
        }
    }

    // ---- reduce both samples; apply deferred layer-3 scale ----
    float p0 = pacc[0], p1 = pacc[1];
#pragma unroll
    for (int o = 16; o; o >>= 1) {
        p0 += __shfl_xor_sync(0xFFFFFFFFu, p0, o);
        p1 += __shfl_xor_sync(0xFFFFFFFFu, p1, o);
    }
    if ((t & 31) == 0) red[t >> 5] = make_float2(p0, p1);
    __syncthreads();
    if (t < 2) {
        float s = 0.f;
#pragma unroll
        for (int w = 0; w < 8; w++) s += (t == 0) ? red[w].x : red[w].y;
        out[2 * b + t] = s * a3[0] + head_b[0];
    }
}

extern "C" void kernel_launch(void* const* d_in, const int* in_sizes, int n_in,
                              void* d_out, int out_size)
{
    const float* inputs = (const float*)d_in[0];
    const float* params = (const float*)d_in[1];
    const float* head_w = (const float*)d_in[2];
    const float* head_b = (const float*)d_in[3];
    float* out = (float*)d_out;

    cudaFuncSetAttribute(qsim10_kernel, cudaFuncAttributeMaxDynamicSharedMemorySize, SMEM_BYTES);
    qsetup_kernel<<<1, 192>>>(params, head_w);           // batch-shared constants
    int B2 = out_size / 2;                               // two samples per block
    qsim10_kernel<<<B2, 256, SMEM_BYTES>>>(inputs, head_w, head_b, out);
}